// round 5
// baseline (speedup 1.0000x reference)
#include <cuda_runtime.h>
#include <cuda_bf16.h>
#include <math.h>
#include <stdint.h>

// Problem constants: B=4, L=1024, DM=768, DC=256, N=16, R=48, K=4, H=8, HD=32

// ======================= scratch buffers (static; no allocation) =======================
__device__ float g_xzy[4096 * 768];
__device__ float g_xc[4096 * 256];
__device__ float g_xdbl[4096 * 80];
__device__ float g_delta[4096 * 256];
__device__ float g_qkv[4096 * 768];

__device__ __nv_bfloat16 g_hsS[4096 * 2304];
__device__ __nv_bfloat16 g_winS[768 * 2304];
__device__ __nv_bfloat16 g_xcS[4096 * 768];
__device__ __nv_bfloat16 g_wxpS[80 * 768];
__device__ __nv_bfloat16 g_dtS[4096 * 144];
__device__ __nv_bfloat16 g_wdtS[256 * 144];
__device__ __nv_bfloat16 g_ycS[4096 * 768];
__device__ __nv_bfloat16 g_wqkvS[768 * 768];
__device__ __nv_bfloat16 g_oS[4096 * 768];
__device__ __nv_bfloat16 g_watS[256 * 768];
__device__ __nv_bfloat16 g_catS[4096 * 2304];
__device__ __nv_bfloat16 g_woutS[768 * 2304];

// ======================= small asm helpers =======================
__device__ __forceinline__ uint32_t smem_to_u32(const void* smem_ptr) {
    uint32_t addr;
    asm("{ .reg .u64 tmp; cvta.to.shared.u64 tmp, %1; cvt.u32.u64 %0, tmp; }"
        : "=r"(addr) : "l"(smem_ptr));
    return addr;
}

__device__ __forceinline__ uint32_t lds32(uint32_t a) {
    uint32_t v;
    asm volatile("ld.shared.b32 %0, [%1];" : "=r"(v) : "r"(a));
    return v;
}

__device__ __forceinline__ void cp16(uint32_t dst, const void* src, bool pred) {
    int sz = pred ? 16 : 0;
    asm volatile("cp.async.cg.shared.global [%0], [%1], 16, %2;"
                 :: "r"(dst), "l"(src), "r"(sz) : "memory");
}

__device__ __forceinline__ void mma16816(float* c, const uint32_t* a, const uint32_t* b) {
    asm volatile(
        "mma.sync.aligned.m16n8k16.row.col.f32.bf16.bf16.f32 "
        "{%0,%1,%2,%3}, {%4,%5,%6,%7}, {%8,%9}, {%0,%1,%2,%3};"
        : "+f"(c[0]), "+f"(c[1]), "+f"(c[2]), "+f"(c[3])
        : "r"(a[0]), "r"(a[1]), "r"(a[2]), "r"(a[3]), "r"(b[0]), "r"(b[1]));
}

__device__ __forceinline__ uint32_t packh(float x, float y) {
    __nv_bfloat162 t = __floats2bfloat162_rn(x, y);
    return *(uint32_t*)&t;
}

__device__ __forceinline__ void split3(float f, __nv_bfloat16& hi, __nv_bfloat16& lo) {
    hi = __float2bfloat16(f);
    lo = __float2bfloat16(f - __bfloat162float(hi));
}

// ======================= split-bf16 conversion (inputs/weights only) =======================
// modeA layout along K': [hi, hi, lo]; modeB: [hi, lo, hi]
__global__ void __launch_bounds__(256) split_kernel(
    const float* __restrict__ src, int ld,
    int M, int K, __nv_bfloat16* __restrict__ dst, int modeB)
{
    int idx = blockIdx.x * 256 + threadIdx.x;
    if (idx >= M * K) return;
    int m = idx / K, k = idx - m * K;
    float f = src[(long long)m * ld + k];
    __nv_bfloat16 hi, lo;
    split3(f, hi, lo);
    __nv_bfloat16* r = dst + (long long)m * 3 * K;
    if (modeB) { r[k] = hi; r[K + k] = lo; r[2 * K + k] = hi; }
    else       { r[k] = hi; r[K + k] = hi; r[2 * K + k] = lo; }
}

// ======================= HMMA bf16 NT GEMM, tile 128x128x32 =======================
// epi: 0 none, 1 +bias*bscale, 2 softplus(v + bias*bscale)
// osplit: if 1, C is a bf16 buffer; write modeA triplet [hi,hi,lo] at coff+c,
//         coff+c+Kof, coff+c+2*Kof (row stride ldc in bf16 elements).
#define ASTR 80
#define STG 20480      // 128*80 (A) + 128*80 (B)
__global__ void __launch_bounds__(256) gemm_mma(
    const __nv_bfloat16* __restrict__ A, const __nv_bfloat16* __restrict__ B,
    float* __restrict__ C, int M, int Nglob, int Kp,
    int lda, int ldb, int ldc, int coff,
    const float* __restrict__ bias, float bscale, float alpha, int epi,
    int osplit, int Kof)
{
    __shared__ __align__(16) char smem[2 * STG];
    uint32_t sb = smem_to_u32(smem);
    int tid = threadIdx.x;
    int m0 = blockIdx.y * 128;
    int n0 = blockIdx.x * 128;
    int NC = (Kp + 31) >> 5;

    auto load_stage = [&](int c, int s) {
        int k0 = c * 32;
        uint32_t ab = sb + s * STG;
        uint32_t bb = ab + 10240;
        #pragma unroll
        for (int i = 0; i < 4; i++) {
            int gg = tid + i * 256;
            int r = gg >> 2, c16 = gg & 3;
            int k = k0 + c16 * 8;
            if (gg < 512) {
                cp16(ab + r * ASTR + c16 * 16, A + (long long)(m0 + r) * lda + k, k < Kp);
            } else {
                int r2 = r - 128;
                cp16(bb + r2 * ASTR + c16 * 16, B + (long long)(n0 + r2) * ldb + k,
                     (n0 + r2) < Nglob && k < Kp);
            }
        }
        asm volatile("cp.async.commit_group;" ::: "memory");
    };

    int wid = tid >> 5, lane = tid & 31;
    int wm = wid & 3, wn = wid >> 2;          // 4x2 warps, warp tile 32x64
    int g = lane >> 2, tg = lane & 3;
    float acc[2][8][4] = {};

    load_stage(0, 0);

    for (int c = 0; c < NC; c++) {
        int s = c & 1;
        if (c + 1 < NC) {
            load_stage(c + 1, s ^ 1);
            asm volatile("cp.async.wait_group 1;" ::: "memory");
        } else {
            asm volatile("cp.async.wait_group 0;" ::: "memory");
        }
        __syncthreads();

        uint32_t ab = sb + s * STG;
        uint32_t bb = ab + 10240;
        #pragma unroll
        for (int ks = 0; ks < 2; ks++) {
            uint32_t a[2][4], b[8][2];
            #pragma unroll
            for (int mi = 0; mi < 2; mi++) {
                uint32_t base = ab + (wm * 32 + mi * 16 + g) * ASTR + ks * 32 + tg * 4;
                a[mi][0] = lds32(base);
                a[mi][1] = lds32(base + 8 * ASTR);
                a[mi][2] = lds32(base + 16);
                a[mi][3] = lds32(base + 8 * ASTR + 16);
            }
            #pragma unroll
            for (int nj = 0; nj < 8; nj++) {
                uint32_t base = bb + (wn * 64 + nj * 8 + g) * ASTR + ks * 32 + tg * 4;
                b[nj][0] = lds32(base);
                b[nj][1] = lds32(base + 16);
            }
            #pragma unroll
            for (int mi = 0; mi < 2; mi++)
                #pragma unroll
                for (int nj = 0; nj < 8; nj++)
                    mma16816(acc[mi][nj], a[mi], b[nj]);
        }
        __syncthreads();
    }

    // ---- epilogue ----
    #pragma unroll
    for (int mi = 0; mi < 2; mi++) {
        int r0 = m0 + wm * 32 + mi * 16 + g;
        #pragma unroll
        for (int nj = 0; nj < 8; nj++) {
            int cc = n0 + wn * 64 + nj * 8 + tg * 2;
            if (cc >= Nglob) continue;
            #pragma unroll
            for (int hh = 0; hh < 2; hh++) {
                int rr = r0 + hh * 8;
                float v0 = acc[mi][nj][hh * 2 + 0] * alpha;
                float v1 = acc[mi][nj][hh * 2 + 1] * alpha;
                if (epi >= 1) { v0 += bias[cc] * bscale; v1 += bias[cc + 1] * bscale; }
                if (epi == 2) {
                    v0 = (v0 > 15.f) ? v0 : log1pf(__expf(v0));
                    v1 = (v1 > 15.f) ? v1 : log1pf(__expf(v1));
                }
                if (!osplit) {
                    *(float2*)&C[(long long)rr * ldc + coff + cc] = make_float2(v0, v1);
                } else {
                    __nv_bfloat16* Cb = (__nv_bfloat16*)C;
                    long long base = (long long)rr * ldc + coff + cc;
                    __nv_bfloat16 h0, l0, h1, l1;
                    split3(v0, h0, l0);
                    split3(v1, h1, l1);
                    Cb[base]           = h0;  Cb[base + 1]           = h1;
                    Cb[base + Kof]     = h0;  Cb[base + Kof + 1]     = h1;
                    Cb[base + 2 * Kof] = l0;  Cb[base + 2 * Kof + 1] = l1;
                }
            }
        }
    }
}

// ======================= fused flash attention (writes split-bf16 oS) =======================
#define SQ 208
#define SV 272
#define OFF_VTH 26624
#define OFF_VTL 35328
#define OFF_RMAX 44032
#define OFF_RSUM 45056
__global__ void __launch_bounds__(256, 1) flash_kernel(
    const float* __restrict__ qkv, __nv_bfloat16* __restrict__ oS)
{
    __shared__ __align__(16) char smem[46080];
    uint32_t sb = smem_to_u32(smem);
    float* rmax = (float*)(smem + OFF_RMAX);
    float* rsum = (float*)(smem + OFF_RSUM);
    int tid = threadIdx.x;
    int wid = tid >> 5, lane = tid & 31;
    int wm = wid & 3, wn = wid >> 2;
    int g = lane >> 2, tg = lane & 3;
    int z = blockIdx.y;
    int b = z >> 3, h = z & 7;
    int q0 = blockIdx.x * 128;
    const float alpha = 0.17677669529663687f;
    const float* qkvb = qkv + (long long)b * 1024 * 768 + h * 32;

    #pragma unroll
    for (int j = 0; j < 16; j++) {
        int i = tid + j * 256;
        int row = i >> 5, d = i & 31;
        float f = qkvb[(long long)(q0 + row) * 768 + d] * alpha;
        __nv_bfloat16 hi, lo;
        split3(f, hi, lo);
        *(__nv_bfloat16*)(smem + row * SQ + d * 2) = hi;
        *(__nv_bfloat16*)(smem + row * SQ + 64 + d * 2) = hi;
        *(__nv_bfloat16*)(smem + row * SQ + 128 + d * 2) = lo;
    }
    __syncthreads();
    uint32_t qa[6][2][4];
    #pragma unroll
    for (int kb = 0; kb < 6; kb++)
        #pragma unroll
        for (int mi = 0; mi < 2; mi++) {
            uint32_t base = sb + (wm * 32 + mi * 16 + g) * SQ + kb * 32 + tg * 4;
            qa[kb][mi][0] = lds32(base);
            qa[kb][mi][1] = lds32(base + 8 * SQ);
            qa[kb][mi][2] = lds32(base + 16);
            qa[kb][mi][3] = lds32(base + 8 * SQ + 16);
        }

    float accO[2][4][4] = {};
    float m_run[2][2] = {{-1e30f, -1e30f}, {-1e30f, -1e30f}};
    float l_run[2][2] = {{0.f, 0.f}, {0.f, 0.f}};

    for (int t = 0; t < 8; t++) {
        int j0 = t * 128;
        __syncthreads();
        #pragma unroll
        for (int j = 0; j < 16; j++) {
            int i = tid + j * 256;
            int key = i >> 5, d = i & 31;
            const float* src = qkvb + (long long)(j0 + key) * 768;
            float kf = src[256 + d];
            __nv_bfloat16 khi, klo;
            split3(kf, khi, klo);
            *(__nv_bfloat16*)(smem + key * SQ + d * 2) = khi;
            *(__nv_bfloat16*)(smem + key * SQ + 64 + d * 2) = klo;
            *(__nv_bfloat16*)(smem + key * SQ + 128 + d * 2) = khi;
            float vf = src[512 + d];
            __nv_bfloat16 vhi, vlo;
            split3(vf, vhi, vlo);
            *(__nv_bfloat16*)(smem + OFF_VTH + d * SV + key * 2) = vhi;
            *(__nv_bfloat16*)(smem + OFF_VTL + d * SV + key * 2) = vlo;
        }
        __syncthreads();

        float accS[2][8][4] = {};
        #pragma unroll
        for (int kb = 0; kb < 6; kb++) {
            uint32_t bfr[8][2];
            #pragma unroll
            for (int nj = 0; nj < 8; nj++) {
                uint32_t base = sb + (wn * 64 + nj * 8 + g) * SQ + kb * 32 + tg * 4;
                bfr[nj][0] = lds32(base);
                bfr[nj][1] = lds32(base + 16);
            }
            #pragma unroll
            for (int mi = 0; mi < 2; mi++)
                #pragma unroll
                for (int nj = 0; nj < 8; nj++)
                    mma16816(accS[mi][nj], qa[kb][mi], bfr[nj]);
        }

        float mx[2][2];
        #pragma unroll
        for (int mi = 0; mi < 2; mi++)
            #pragma unroll
            for (int hh = 0; hh < 2; hh++) {
                float m = -1e30f;
                #pragma unroll
                for (int nj = 0; nj < 8; nj++)
                    m = fmaxf(m, fmaxf(accS[mi][nj][hh * 2], accS[mi][nj][hh * 2 + 1]));
                m = fmaxf(m, __shfl_xor_sync(0xffffffffu, m, 1));
                m = fmaxf(m, __shfl_xor_sync(0xffffffffu, m, 2));
                mx[mi][hh] = m;
            }
        if (tg == 0) {
            #pragma unroll
            for (int mi = 0; mi < 2; mi++)
                #pragma unroll
                for (int hh = 0; hh < 2; hh++)
                    rmax[wn * 128 + wm * 32 + mi * 16 + hh * 8 + g] = mx[mi][hh];
        }
        __syncthreads();

        float fsc[2][2], mnew[2][2], ls[2][2];
        #pragma unroll
        for (int mi = 0; mi < 2; mi++)
            #pragma unroll
            for (int hh = 0; hh < 2; hh++) {
                int r = wm * 32 + mi * 16 + hh * 8 + g;
                float tm = fmaxf(rmax[r], rmax[128 + r]);
                float mn = fmaxf(m_run[mi][hh], tm);
                mnew[mi][hh] = mn;
                fsc[mi][hh] = __expf(m_run[mi][hh] - mn);
                ls[mi][hh] = 0.f;
            }
        #pragma unroll
        for (int mi = 0; mi < 2; mi++)
            #pragma unroll
            for (int hh = 0; hh < 2; hh++) {
                float mn = mnew[mi][hh];
                float s = 0.f;
                #pragma unroll
                for (int nj = 0; nj < 8; nj++) {
                    float p0 = __expf(accS[mi][nj][hh * 2] - mn);
                    float p1 = __expf(accS[mi][nj][hh * 2 + 1] - mn);
                    accS[mi][nj][hh * 2] = p0;
                    accS[mi][nj][hh * 2 + 1] = p1;
                    s += p0 + p1;
                }
                ls[mi][hh] = s;
                float f = fsc[mi][hh];
                #pragma unroll
                for (int nj2 = 0; nj2 < 4; nj2++) {
                    accO[mi][nj2][hh * 2] *= f;
                    accO[mi][nj2][hh * 2 + 1] *= f;
                }
            }
        #pragma unroll
        for (int mi = 0; mi < 2; mi++)
            #pragma unroll
            for (int hh = 0; hh < 2; hh++) {
                float s = ls[mi][hh];
                s += __shfl_xor_sync(0xffffffffu, s, 1);
                s += __shfl_xor_sync(0xffffffffu, s, 2);
                ls[mi][hh] = s;
            }
        if (tg == 0) {
            #pragma unroll
            for (int mi = 0; mi < 2; mi++)
                #pragma unroll
                for (int hh = 0; hh < 2; hh++)
                    rsum[wn * 128 + wm * 32 + mi * 16 + hh * 8 + g] = ls[mi][hh];
        }
        __syncthreads();
        #pragma unroll
        for (int mi = 0; mi < 2; mi++)
            #pragma unroll
            for (int hh = 0; hh < 2; hh++) {
                int r = wm * 32 + mi * 16 + hh * 8 + g;
                l_run[mi][hh] = l_run[mi][hh] * fsc[mi][hh] + rsum[r] + rsum[128 + r];
                m_run[mi][hh] = mnew[mi][hh];
            }

        #pragma unroll
        for (int kb = 0; kb < 4; kb++) {
            uint32_t pah[2][4], pal[2][4];
            #pragma unroll
            for (int mi = 0; mi < 2; mi++) {
                float x0 = accS[mi][2 * kb][0], x1 = accS[mi][2 * kb][1];
                float x2 = accS[mi][2 * kb][2], x3 = accS[mi][2 * kb][3];
                float y0 = accS[mi][2 * kb + 1][0], y1 = accS[mi][2 * kb + 1][1];
                float y2 = accS[mi][2 * kb + 1][2], y3 = accS[mi][2 * kb + 1][3];
                pah[mi][0] = packh(x0, x1);
                pah[mi][1] = packh(x2, x3);
                pah[mi][2] = packh(y0, y1);
                pah[mi][3] = packh(y2, y3);
                __nv_bfloat162 t0 = *(__nv_bfloat162*)&pah[mi][0];
                __nv_bfloat162 t1 = *(__nv_bfloat162*)&pah[mi][1];
                __nv_bfloat162 t2 = *(__nv_bfloat162*)&pah[mi][2];
                __nv_bfloat162 t3 = *(__nv_bfloat162*)&pah[mi][3];
                pal[mi][0] = packh(x0 - __bfloat162float(t0.x), x1 - __bfloat162float(t0.y));
                pal[mi][1] = packh(x2 - __bfloat162float(t1.x), x3 - __bfloat162float(t1.y));
                pal[mi][2] = packh(y0 - __bfloat162float(t2.x), y1 - __bfloat162float(t2.y));
                pal[mi][3] = packh(y2 - __bfloat162float(t3.x), y3 - __bfloat162float(t3.y));
            }
            uint32_t vbh[4][2], vbl[4][2];
            int kcol = (wn * 64 + kb * 16 + tg * 2) * 2;
            #pragma unroll
            for (int nj2 = 0; nj2 < 4; nj2++) {
                uint32_t bh = sb + OFF_VTH + (nj2 * 8 + g) * SV + kcol;
                uint32_t bl = sb + OFF_VTL + (nj2 * 8 + g) * SV + kcol;
                vbh[nj2][0] = lds32(bh);  vbh[nj2][1] = lds32(bh + 16);
                vbl[nj2][0] = lds32(bl);  vbl[nj2][1] = lds32(bl + 16);
            }
            #pragma unroll
            for (int mi = 0; mi < 2; mi++)
                #pragma unroll
                for (int nj2 = 0; nj2 < 4; nj2++) {
                    mma16816(accO[mi][nj2], pah[mi], vbh[nj2]);
                    mma16816(accO[mi][nj2], pah[mi], vbl[nj2]);
                    mma16816(accO[mi][nj2], pal[mi], vbh[nj2]);
                }
        }
    }

    // ---- cross-warp O reduction + normalize + split store to oS ----
    __syncthreads();
    float* Ob = (float*)smem;
    if (wn == 0) {
        #pragma unroll
        for (int mi = 0; mi < 2; mi++)
            #pragma unroll
            for (int hh = 0; hh < 2; hh++) {
                int r = wm * 32 + mi * 16 + hh * 8 + g;
                #pragma unroll
                for (int nj2 = 0; nj2 < 4; nj2++) {
                    Ob[r * 36 + nj2 * 8 + tg * 2]     = accO[mi][nj2][hh * 2];
                    Ob[r * 36 + nj2 * 8 + tg * 2 + 1] = accO[mi][nj2][hh * 2 + 1];
                }
            }
    }
    __syncthreads();
    if (wn == 1) {
        #pragma unroll
        for (int mi = 0; mi < 2; mi++)
            #pragma unroll
            for (int hh = 0; hh < 2; hh++) {
                int r = wm * 32 + mi * 16 + hh * 8 + g;
                float inv = 1.f / l_run[mi][hh];
                #pragma unroll
                for (int nj2 = 0; nj2 < 4; nj2++) {
                    int d = nj2 * 8 + tg * 2;
                    float v0 = (Ob[r * 36 + d]     + accO[mi][nj2][hh * 2])     * inv;
                    float v1 = (Ob[r * 36 + d + 1] + accO[mi][nj2][hh * 2 + 1]) * inv;
                    __nv_bfloat16 h0, l0, h1, l1;
                    split3(v0, h0, l0);
                    split3(v1, h1, l1);
                    long long base = (long long)(b * 1024 + q0 + r) * 768 + h * 32 + d;
                    oS[base]       = h0;  oS[base + 1]       = h1;
                    oS[base + 256] = h0;  oS[base + 256 + 1] = h1;
                    oS[base + 512] = l0;  oS[base + 512 + 1] = l1;
                }
            }
    }
}

// ======================= depthwise conv + SiLU, fused split outputs =======================
__global__ void __launch_bounds__(256) conv_silu_kernel(
    const float* __restrict__ xzy,
    const float* __restrict__ wx, const float* __restrict__ wz, const float* __restrict__ wy,
    float* __restrict__ xc, __nv_bfloat16* __restrict__ xcS,
    __nv_bfloat16* __restrict__ catS, __nv_bfloat16* __restrict__ ycS)
{
    int idx = blockIdx.x * 256 + threadIdx.x;
    int d = idx & 255;
    int m = idx >> 8;
    int l = m & 1023;
    const float* base = xzy + (long long)m * 768;
    float a0 = 0.f, a1 = 0.f, a2 = 0.f;
    #pragma unroll
    for (int k = 0; k < 4; k++) {
        int li = l + k - 1;
        if (li < 0 || li >= 1024) continue;
        const float* row = base + (long long)(k - 1) * 768;
        a0 = fmaf(row[d],       wx[d * 4 + k], a0);
        a1 = fmaf(row[256 + d], wz[d * 4 + k], a1);
        a2 = fmaf(row[512 + d], wy[d * 4 + k], a2);
    }
    a0 = a0 / (1.f + __expf(-a0));
    a1 = a1 / (1.f + __expf(-a1));
    a2 = a2 / (1.f + __expf(-a2));
    xc[idx] = a0;                              // fp32 for the scan
    __nv_bfloat16 hi, lo;
    split3(a0, hi, lo);                        // xcS modeA (stride 768)
    xcS[(long long)m * 768 + d] = hi;
    xcS[(long long)m * 768 + 256 + d] = hi;
    xcS[(long long)m * 768 + 512 + d] = lo;
    split3(a1, hi, lo);                        // z -> catS cols [256,512) modeA (stride 2304)
    catS[(long long)m * 2304 + 256 + d] = hi;
    catS[(long long)m * 2304 + 768 + 256 + d] = hi;
    catS[(long long)m * 2304 + 1536 + 256 + d] = lo;
    split3(a2, hi, lo);                        // ycS modeA
    ycS[(long long)m * 768 + d] = hi;
    ycS[(long long)m * 768 + 256 + d] = hi;
    ycS[(long long)m * 768 + 512 + d] = lo;
}

// ======================= selective scan (writes split into catS cols [0,256)) =======================
__global__ void __launch_bounds__(256) scan_kernel(
    const float* __restrict__ delta, const float* __restrict__ xc,
    const float* __restrict__ xdbl, const float* __restrict__ A_log,
    const float* __restrict__ D_param, __nv_bfloat16* __restrict__ catS)
{
    int t = blockIdx.x * 256 + threadIdx.x;
    int lane = t & 15;
    int p = t >> 4;
    int b = p >> 8;
    int d = p & 255;
    float Acoef = -__expf(A_log[d * 16 + lane]);
    float Dd = D_param[d];
    float h = 0.f;
    const float* dptr = delta + (long long)b * 1024 * 256 + d;
    const float* xptr = xc    + (long long)b * 1024 * 256 + d;
    const float* bptr = xdbl  + (long long)b * 1024 * 80 + 48 + lane;
    const float* cptr = bptr + 16;
    __nv_bfloat16* optr = catS + (long long)b * 1024 * 2304 + d;
    #pragma unroll 4
    for (int l = 0; l < 1024; l++) {
        float dl = dptr[(long long)l * 256];
        float xv = xptr[(long long)l * 256];
        float Bv = bptr[(long long)l * 80];
        float Cv = cptr[(long long)l * 80];
        float dA = __expf(dl * Acoef);
        h = fmaf(dA, h, dl * xv * Bv);
        float yv = h * Cv;
        yv += __shfl_xor_sync(0xffffffffu, yv, 1);
        yv += __shfl_xor_sync(0xffffffffu, yv, 2);
        yv += __shfl_xor_sync(0xffffffffu, yv, 4);
        yv += __shfl_xor_sync(0xffffffffu, yv, 8);
        if (lane == 0) {
            float v = fmaf(xv, Dd, yv);
            __nv_bfloat16 hi, lo;
            split3(v, hi, lo);
            optr[(long long)l * 2304] = hi;
            optr[(long long)l * 2304 + 768] = hi;
            optr[(long long)l * 2304 + 1536] = lo;
        }
    }
}

// ======================= host launcher =======================
extern "C" void kernel_launch(void* const* d_in, const int* in_sizes, int n_in,
                              void* d_out, int out_size)
{
    const float* hs          = (const float*)d_in[0];
    const float* in_proj_w   = (const float*)d_in[1];
    const float* conv_wx     = (const float*)d_in[2];
    const float* conv_wz     = (const float*)d_in[3];
    const float* conv_wy     = (const float*)d_in[4];
    const float* x_proj_w    = (const float*)d_in[5];
    const float* dt_proj_w   = (const float*)d_in[6];
    const float* dt_proj_b   = (const float*)d_in[7];
    const float* A_log       = (const float*)d_in[8];
    const float* D_param     = (const float*)d_in[9];
    const float* out_proj_w  = (const float*)d_in[10];
    const float* qkv_w       = (const float*)d_in[11];
    const float* attn_proj_w = (const float*)d_in[12];
    const float* attn_proj_b = (const float*)d_in[13];
    float* out = (float*)d_out;

    float *xzy, *xc, *xdbl, *delta, *qkv;
    cudaGetSymbolAddress((void**)&xzy,   g_xzy);
    cudaGetSymbolAddress((void**)&xc,    g_xc);
    cudaGetSymbolAddress((void**)&xdbl,  g_xdbl);
    cudaGetSymbolAddress((void**)&delta, g_delta);
    cudaGetSymbolAddress((void**)&qkv,   g_qkv);

    __nv_bfloat16 *hsS, *winS, *xcS, *wxpS, *dtS, *wdtS, *ycS, *wqkvS;
    __nv_bfloat16 *oS, *watS, *catS, *woutS;
    cudaGetSymbolAddress((void**)&hsS,   g_hsS);
    cudaGetSymbolAddress((void**)&winS,  g_winS);
    cudaGetSymbolAddress((void**)&xcS,   g_xcS);
    cudaGetSymbolAddress((void**)&wxpS,  g_wxpS);
    cudaGetSymbolAddress((void**)&dtS,   g_dtS);
    cudaGetSymbolAddress((void**)&wdtS,  g_wdtS);
    cudaGetSymbolAddress((void**)&ycS,   g_ycS);
    cudaGetSymbolAddress((void**)&wqkvS, g_wqkvS);
    cudaGetSymbolAddress((void**)&oS,    g_oS);
    cudaGetSymbolAddress((void**)&watS,  g_watS);
    cudaGetSymbolAddress((void**)&catS,  g_catS);
    cudaGetSymbolAddress((void**)&woutS, g_woutS);

    // 1) in_proj: xzy = hs @ in_proj_w^T   (4096x768, Kp=2304)
    split_kernel<<<12288, 256>>>(hs, 768, 4096, 768, hsS, 0);
    split_kernel<<<2304, 256>>>(in_proj_w, 768, 768, 768, winS, 1);
    gemm_mma<<<dim3(6, 32), 256>>>(hsS, winS, xzy, 4096, 768, 2304,
        2304, 2304, 768, 0, nullptr, 0.f, 1.f, 0, 0, 0);

    // 2) depthwise conv + SiLU (fused split outputs)
    conv_silu_kernel<<<4096, 256>>>(xzy, conv_wx, conv_wz, conv_wy, xc, xcS, catS, ycS);

    // 3) x_dbl = xc @ x_proj_w^T   (4096x80, Kp=768)
    split_kernel<<<80, 256>>>(x_proj_w, 256, 80, 256, wxpS, 1);
    gemm_mma<<<dim3(1, 32), 256>>>(xcS, wxpS, xdbl, 4096, 80, 768,
        768, 768, 80, 0, nullptr, 0.f, 1.f, 0, 0, 0);

    // 4) delta = softplus(dt @ dt_proj_w^T + 2*dt_proj_b)   (Kp=144)
    split_kernel<<<768, 256>>>(xdbl, 80, 4096, 48, dtS, 0);
    split_kernel<<<48, 256>>>(dt_proj_w, 48, 256, 48, wdtS, 1);
    gemm_mma<<<dim3(2, 32), 256>>>(dtS, wdtS, delta, 4096, 256, 144,
        144, 144, 256, 0, dt_proj_b, 2.f, 1.f, 2, 0, 0);

    // 5) selective scan -> catS cols [0,256) (split)
    scan_kernel<<<64, 256>>>(delta, xc, xdbl, A_log, D_param, catS);

    // 6) qkv = yc @ qkv_w^T   (4096x768, Kp=768)
    split_kernel<<<768, 256>>>(qkv_w, 256, 768, 256, wqkvS, 1);
    gemm_mma<<<dim3(6, 32), 256>>>(ycS, wqkvS, qkv, 4096, 768, 768,
        768, 768, 768, 0, nullptr, 0.f, 1.f, 0, 0, 0);

    // 7) fused flash attention -> oS (split, 4096x[3x256])
    flash_kernel<<<dim3(8, 32), 256>>>(qkv, oS);

    // 8) y_att = o @ attn_proj_w^T + b -> catS cols [512,768) (split epilogue)
    split_kernel<<<256, 256>>>(attn_proj_w, 256, 256, 256, watS, 1);
    gemm_mma<<<dim3(2, 32), 256>>>(oS, watS, (float*)catS, 4096, 256, 768,
        768, 768, 2304, 512, attn_proj_b, 1.f, 1.f, 1, 1, 768);

    // 9) out = catS @ out_proj_w^T   (Kp=2304)
    split_kernel<<<2304, 256>>>(out_proj_w, 768, 768, 768, woutS, 1);
    gemm_mma<<<dim3(6, 32), 256>>>(catS, woutS, out, 4096, 768, 2304,
        2304, 2304, 768, 0, nullptr, 0.f, 1.f, 0, 0, 0);
}

// round 6
// speedup vs baseline: 1.0935x; 1.0935x over previous
#include <cuda_runtime.h>
#include <cuda_bf16.h>
#include <math.h>
#include <stdint.h>

// Problem constants: B=4, L=1024, DM=768, DC=256, N=16, R=48, K=4, H=8, HD=32

// ======================= scratch buffers (static; no allocation) =======================
__device__ float g_xzy[4096 * 768];
__device__ float g_xc[4096 * 256];
__device__ float g_xdbl[4096 * 80];
__device__ float g_delta[4096 * 256];
__device__ float g_qkv[4096 * 768];

__device__ __nv_bfloat16 g_hsS[4096 * 2304];
__device__ __nv_bfloat16 g_winS[768 * 2304];
__device__ __nv_bfloat16 g_xcS[4096 * 768];
__device__ __nv_bfloat16 g_wxpS[80 * 768];
__device__ __nv_bfloat16 g_dtS[4096 * 144];
__device__ __nv_bfloat16 g_wdtS[256 * 144];
__device__ __nv_bfloat16 g_ycS[4096 * 768];
__device__ __nv_bfloat16 g_wqkvS[768 * 768];
__device__ __nv_bfloat16 g_oS[4096 * 768];
__device__ __nv_bfloat16 g_watS[256 * 768];
__device__ __nv_bfloat16 g_catS[4096 * 2304];
__device__ __nv_bfloat16 g_woutS[768 * 2304];

// ======================= small asm helpers =======================
__device__ __forceinline__ uint32_t smem_to_u32(const void* smem_ptr) {
    uint32_t addr;
    asm("{ .reg .u64 tmp; cvta.to.shared.u64 tmp, %1; cvt.u32.u64 %0, tmp; }"
        : "=r"(addr) : "l"(smem_ptr));
    return addr;
}

__device__ __forceinline__ uint32_t lds32(uint32_t a) {
    uint32_t v;
    asm volatile("ld.shared.b32 %0, [%1];" : "=r"(v) : "r"(a));
    return v;
}

__device__ __forceinline__ void cp16(uint32_t dst, const void* src, bool pred) {
    int sz = pred ? 16 : 0;
    asm volatile("cp.async.cg.shared.global [%0], [%1], 16, %2;"
                 :: "r"(dst), "l"(src), "r"(sz) : "memory");
}

__device__ __forceinline__ void mma16816(float* c, const uint32_t* a, const uint32_t* b) {
    asm volatile(
        "mma.sync.aligned.m16n8k16.row.col.f32.bf16.bf16.f32 "
        "{%0,%1,%2,%3}, {%4,%5,%6,%7}, {%8,%9}, {%0,%1,%2,%3};"
        : "+f"(c[0]), "+f"(c[1]), "+f"(c[2]), "+f"(c[3])
        : "r"(a[0]), "r"(a[1]), "r"(a[2]), "r"(a[3]), "r"(b[0]), "r"(b[1]));
}

__device__ __forceinline__ uint32_t packh(float x, float y) {
    __nv_bfloat162 t = __floats2bfloat162_rn(x, y);
    return *(uint32_t*)&t;
}

__device__ __forceinline__ void split3(float f, __nv_bfloat16& hi, __nv_bfloat16& lo) {
    hi = __float2bfloat16(f);
    lo = __float2bfloat16(f - __bfloat162float(hi));
}

// ======================= split-bf16 conversion (inputs/weights only) =======================
// modeA layout along K': [hi, hi, lo]; modeB: [hi, lo, hi]
__global__ void __launch_bounds__(256) split_kernel(
    const float* __restrict__ src, int ld,
    int M, int K, __nv_bfloat16* __restrict__ dst, int modeB)
{
    int idx = blockIdx.x * 256 + threadIdx.x;
    if (idx >= M * K) return;
    int m = idx / K, k = idx - m * K;
    float f = src[(long long)m * ld + k];
    __nv_bfloat16 hi, lo;
    split3(f, hi, lo);
    __nv_bfloat16* r = dst + (long long)m * 3 * K;
    if (modeB) { r[k] = hi; r[K + k] = lo; r[2 * K + k] = hi; }
    else       { r[k] = hi; r[K + k] = hi; r[2 * K + k] = lo; }
}

// ======================= HMMA bf16 NT GEMM, tile 128x64x32 (round-3 proven engine) ==========
// epi: 0 none, 1 +bias*bscale, 2 softplus(v + bias*bscale)
// osplit: if 1, C is a bf16 buffer; write modeA triplet [hi,hi,lo] at coff+c,
//         coff+c+Kof, coff+c+2*Kof (row stride ldc in bf16 elements).
#define ASTR 80
#define STG 15360      // 128*80 (A) + 64*80 (B)
__global__ void __launch_bounds__(256) gemm_mma(
    const __nv_bfloat16* __restrict__ A, const __nv_bfloat16* __restrict__ B,
    float* __restrict__ C, int M, int Nglob, int Kp,
    int lda, int ldb, int ldc, int coff,
    const float* __restrict__ bias, float bscale, float alpha, int epi,
    int osplit, int Kof)
{
    __shared__ __align__(16) char smem[2 * STG];
    uint32_t sb = smem_to_u32(smem);
    int tid = threadIdx.x;
    int m0 = blockIdx.y * 128;
    int n0 = blockIdx.x * 64;
    int NC = (Kp + 31) >> 5;

    auto load_stage = [&](int c, int s) {
        int k0 = c * 32;
        uint32_t ab = sb + s * STG;
        uint32_t bb = ab + 10240;
        #pragma unroll
        for (int i = 0; i < 2; i++) {
            int gg = tid + i * 256;
            int r = gg >> 2, c16 = gg & 3;
            int k = k0 + c16 * 8;
            cp16(ab + r * ASTR + c16 * 16, A + (long long)(m0 + r) * lda + k, k < Kp);
        }
        {
            int r = tid >> 2, c16 = tid & 3;
            int k = k0 + c16 * 8;
            cp16(bb + r * ASTR + c16 * 16, B + (long long)(n0 + r) * ldb + k,
                 (n0 + r) < Nglob && k < Kp);
        }
        asm volatile("cp.async.commit_group;" ::: "memory");
    };

    int wid = tid >> 5, lane = tid & 31;
    int wm = wid & 3, wn = wid >> 2;          // 4x2 warps, warp tile 32x32
    int g = lane >> 2, tg = lane & 3;
    float acc[2][4][4] = {};

    load_stage(0, 0);

    for (int c = 0; c < NC; c++) {
        int s = c & 1;
        if (c + 1 < NC) {
            load_stage(c + 1, s ^ 1);
            asm volatile("cp.async.wait_group 1;" ::: "memory");
        } else {
            asm volatile("cp.async.wait_group 0;" ::: "memory");
        }
        __syncthreads();

        uint32_t ab = sb + s * STG;
        uint32_t bb = ab + 10240;
        #pragma unroll
        for (int ks = 0; ks < 2; ks++) {
            uint32_t a[2][4], b[4][2];
            #pragma unroll
            for (int mi = 0; mi < 2; mi++) {
                uint32_t base = ab + (wm * 32 + mi * 16 + g) * ASTR + ks * 32 + tg * 4;
                a[mi][0] = lds32(base);
                a[mi][1] = lds32(base + 8 * ASTR);
                a[mi][2] = lds32(base + 16);
                a[mi][3] = lds32(base + 8 * ASTR + 16);
            }
            #pragma unroll
            for (int nj = 0; nj < 4; nj++) {
                uint32_t base = bb + (wn * 32 + nj * 8 + g) * ASTR + ks * 32 + tg * 4;
                b[nj][0] = lds32(base);
                b[nj][1] = lds32(base + 16);
            }
            #pragma unroll
            for (int mi = 0; mi < 2; mi++)
                #pragma unroll
                for (int nj = 0; nj < 4; nj++)
                    mma16816(acc[mi][nj], a[mi], b[nj]);
        }
        __syncthreads();
    }

    // ---- epilogue ----
    #pragma unroll
    for (int mi = 0; mi < 2; mi++) {
        int r0 = m0 + wm * 32 + mi * 16 + g;
        #pragma unroll
        for (int nj = 0; nj < 4; nj++) {
            int cc = n0 + wn * 32 + nj * 8 + tg * 2;
            if (cc >= Nglob) continue;
            #pragma unroll
            for (int hh = 0; hh < 2; hh++) {
                int rr = r0 + hh * 8;
                float v0 = acc[mi][nj][hh * 2 + 0] * alpha;
                float v1 = acc[mi][nj][hh * 2 + 1] * alpha;
                if (epi >= 1) { v0 += bias[cc] * bscale; v1 += bias[cc + 1] * bscale; }
                if (epi == 2) {
                    v0 = (v0 > 15.f) ? v0 : log1pf(__expf(v0));
                    v1 = (v1 > 15.f) ? v1 : log1pf(__expf(v1));
                }
                if (!osplit) {
                    *(float2*)&C[(long long)rr * ldc + coff + cc] = make_float2(v0, v1);
                } else {
                    __nv_bfloat16* Cb = (__nv_bfloat16*)C;
                    long long base = (long long)rr * ldc + coff + cc;
                    __nv_bfloat16 h0, l0, h1, l1;
                    split3(v0, h0, l0);
                    split3(v1, h1, l1);
                    Cb[base]           = h0;  Cb[base + 1]           = h1;
                    Cb[base + Kof]     = h0;  Cb[base + Kof + 1]     = h1;
                    Cb[base + 2 * Kof] = l0;  Cb[base + 2 * Kof + 1] = l1;
                }
            }
        }
    }
}

// ======================= fused flash attention (writes split-bf16 oS) =======================
#define SQ 208
#define SV 272
#define OFF_VTH 26624
#define OFF_VTL 35328
#define OFF_RMAX 44032
#define OFF_RSUM 45056
__global__ void __launch_bounds__(256, 1) flash_kernel(
    const float* __restrict__ qkv, __nv_bfloat16* __restrict__ oS)
{
    __shared__ __align__(16) char smem[46080];
    uint32_t sb = smem_to_u32(smem);
    float* rmax = (float*)(smem + OFF_RMAX);
    float* rsum = (float*)(smem + OFF_RSUM);
    int tid = threadIdx.x;
    int wid = tid >> 5, lane = tid & 31;
    int wm = wid & 3, wn = wid >> 2;
    int g = lane >> 2, tg = lane & 3;
    int z = blockIdx.y;
    int b = z >> 3, h = z & 7;
    int q0 = blockIdx.x * 128;
    const float alpha = 0.17677669529663687f;
    const float* qkvb = qkv + (long long)b * 1024 * 768 + h * 32;

    #pragma unroll
    for (int j = 0; j < 16; j++) {
        int i = tid + j * 256;
        int row = i >> 5, d = i & 31;
        float f = qkvb[(long long)(q0 + row) * 768 + d] * alpha;
        __nv_bfloat16 hi, lo;
        split3(f, hi, lo);
        *(__nv_bfloat16*)(smem + row * SQ + d * 2) = hi;
        *(__nv_bfloat16*)(smem + row * SQ + 64 + d * 2) = hi;
        *(__nv_bfloat16*)(smem + row * SQ + 128 + d * 2) = lo;
    }
    __syncthreads();
    uint32_t qa[6][2][4];
    #pragma unroll
    for (int kb = 0; kb < 6; kb++)
        #pragma unroll
        for (int mi = 0; mi < 2; mi++) {
            uint32_t base = sb + (wm * 32 + mi * 16 + g) * SQ + kb * 32 + tg * 4;
            qa[kb][mi][0] = lds32(base);
            qa[kb][mi][1] = lds32(base + 8 * SQ);
            qa[kb][mi][2] = lds32(base + 16);
            qa[kb][mi][3] = lds32(base + 8 * SQ + 16);
        }

    float accO[2][4][4] = {};
    float m_run[2][2] = {{-1e30f, -1e30f}, {-1e30f, -1e30f}};
    float l_run[2][2] = {{0.f, 0.f}, {0.f, 0.f}};

    for (int t = 0; t < 8; t++) {
        int j0 = t * 128;
        __syncthreads();
        #pragma unroll
        for (int j = 0; j < 16; j++) {
            int i = tid + j * 256;
            int key = i >> 5, d = i & 31;
            const float* src = qkvb + (long long)(j0 + key) * 768;
            float kf = src[256 + d];
            __nv_bfloat16 khi, klo;
            split3(kf, khi, klo);
            *(__nv_bfloat16*)(smem + key * SQ + d * 2) = khi;
            *(__nv_bfloat16*)(smem + key * SQ + 64 + d * 2) = klo;
            *(__nv_bfloat16*)(smem + key * SQ + 128 + d * 2) = khi;
            float vf = src[512 + d];
            __nv_bfloat16 vhi, vlo;
            split3(vf, vhi, vlo);
            *(__nv_bfloat16*)(smem + OFF_VTH + d * SV + key * 2) = vhi;
            *(__nv_bfloat16*)(smem + OFF_VTL + d * SV + key * 2) = vlo;
        }
        __syncthreads();

        float accS[2][8][4] = {};
        #pragma unroll
        for (int kb = 0; kb < 6; kb++) {
            uint32_t bfr[8][2];
            #pragma unroll
            for (int nj = 0; nj < 8; nj++) {
                uint32_t base = sb + (wn * 64 + nj * 8 + g) * SQ + kb * 32 + tg * 4;
                bfr[nj][0] = lds32(base);
                bfr[nj][1] = lds32(base + 16);
            }
            #pragma unroll
            for (int mi = 0; mi < 2; mi++)
                #pragma unroll
                for (int nj = 0; nj < 8; nj++)
                    mma16816(accS[mi][nj], qa[kb][mi], bfr[nj]);
        }

        float mx[2][2];
        #pragma unroll
        for (int mi = 0; mi < 2; mi++)
            #pragma unroll
            for (int hh = 0; hh < 2; hh++) {
                float m = -1e30f;
                #pragma unroll
                for (int nj = 0; nj < 8; nj++)
                    m = fmaxf(m, fmaxf(accS[mi][nj][hh * 2], accS[mi][nj][hh * 2 + 1]));
                m = fmaxf(m, __shfl_xor_sync(0xffffffffu, m, 1));
                m = fmaxf(m, __shfl_xor_sync(0xffffffffu, m, 2));
                mx[mi][hh] = m;
            }
        if (tg == 0) {
            #pragma unroll
            for (int mi = 0; mi < 2; mi++)
                #pragma unroll
                for (int hh = 0; hh < 2; hh++)
                    rmax[wn * 128 + wm * 32 + mi * 16 + hh * 8 + g] = mx[mi][hh];
        }
        __syncthreads();

        float fsc[2][2], mnew[2][2], ls[2][2];
        #pragma unroll
        for (int mi = 0; mi < 2; mi++)
            #pragma unroll
            for (int hh = 0; hh < 2; hh++) {
                int r = wm * 32 + mi * 16 + hh * 8 + g;
                float tm = fmaxf(rmax[r], rmax[128 + r]);
                float mn = fmaxf(m_run[mi][hh], tm);
                mnew[mi][hh] = mn;
                fsc[mi][hh] = __expf(m_run[mi][hh] - mn);
                ls[mi][hh] = 0.f;
            }
        #pragma unroll
        for (int mi = 0; mi < 2; mi++)
            #pragma unroll
            for (int hh = 0; hh < 2; hh++) {
                float mn = mnew[mi][hh];
                float s = 0.f;
                #pragma unroll
                for (int nj = 0; nj < 8; nj++) {
                    float p0 = __expf(accS[mi][nj][hh * 2] - mn);
                    float p1 = __expf(accS[mi][nj][hh * 2 + 1] - mn);
                    accS[mi][nj][hh * 2] = p0;
                    accS[mi][nj][hh * 2 + 1] = p1;
                    s += p0 + p1;
                }
                ls[mi][hh] = s;
                float f = fsc[mi][hh];
                #pragma unroll
                for (int nj2 = 0; nj2 < 4; nj2++) {
                    accO[mi][nj2][hh * 2] *= f;
                    accO[mi][nj2][hh * 2 + 1] *= f;
                }
            }
        #pragma unroll
        for (int mi = 0; mi < 2; mi++)
            #pragma unroll
            for (int hh = 0; hh < 2; hh++) {
                float s = ls[mi][hh];
                s += __shfl_xor_sync(0xffffffffu, s, 1);
                s += __shfl_xor_sync(0xffffffffu, s, 2);
                ls[mi][hh] = s;
            }
        if (tg == 0) {
            #pragma unroll
            for (int mi = 0; mi < 2; mi++)
                #pragma unroll
                for (int hh = 0; hh < 2; hh++)
                    rsum[wn * 128 + wm * 32 + mi * 16 + hh * 8 + g] = ls[mi][hh];
        }
        __syncthreads();
        #pragma unroll
        for (int mi = 0; mi < 2; mi++)
            #pragma unroll
            for (int hh = 0; hh < 2; hh++) {
                int r = wm * 32 + mi * 16 + hh * 8 + g;
                l_run[mi][hh] = l_run[mi][hh] * fsc[mi][hh] + rsum[r] + rsum[128 + r];
                m_run[mi][hh] = mnew[mi][hh];
            }

        #pragma unroll
        for (int kb = 0; kb < 4; kb++) {
            uint32_t pah[2][4], pal[2][4];
            #pragma unroll
            for (int mi = 0; mi < 2; mi++) {
                float x0 = accS[mi][2 * kb][0], x1 = accS[mi][2 * kb][1];
                float x2 = accS[mi][2 * kb][2], x3 = accS[mi][2 * kb][3];
                float y0 = accS[mi][2 * kb + 1][0], y1 = accS[mi][2 * kb + 1][1];
                float y2 = accS[mi][2 * kb + 1][2], y3 = accS[mi][2 * kb + 1][3];
                pah[mi][0] = packh(x0, x1);
                pah[mi][1] = packh(x2, x3);
                pah[mi][2] = packh(y0, y1);
                pah[mi][3] = packh(y2, y3);
                __nv_bfloat162 t0 = *(__nv_bfloat162*)&pah[mi][0];
                __nv_bfloat162 t1 = *(__nv_bfloat162*)&pah[mi][1];
                __nv_bfloat162 t2 = *(__nv_bfloat162*)&pah[mi][2];
                __nv_bfloat162 t3 = *(__nv_bfloat162*)&pah[mi][3];
                pal[mi][0] = packh(x0 - __bfloat162float(t0.x), x1 - __bfloat162float(t0.y));
                pal[mi][1] = packh(x2 - __bfloat162float(t1.x), x3 - __bfloat162float(t1.y));
                pal[mi][2] = packh(y0 - __bfloat162float(t2.x), y1 - __bfloat162float(t2.y));
                pal[mi][3] = packh(y2 - __bfloat162float(t3.x), y3 - __bfloat162float(t3.y));
            }
            uint32_t vbh[4][2], vbl[4][2];
            int kcol = (wn * 64 + kb * 16 + tg * 2) * 2;
            #pragma unroll
            for (int nj2 = 0; nj2 < 4; nj2++) {
                uint32_t bh = sb + OFF_VTH + (nj2 * 8 + g) * SV + kcol;
                uint32_t bl = sb + OFF_VTL + (nj2 * 8 + g) * SV + kcol;
                vbh[nj2][0] = lds32(bh);  vbh[nj2][1] = lds32(bh + 16);
                vbl[nj2][0] = lds32(bl);  vbl[nj2][1] = lds32(bl + 16);
            }
            #pragma unroll
            for (int mi = 0; mi < 2; mi++)
                #pragma unroll
                for (int nj2 = 0; nj2 < 4; nj2++) {
                    mma16816(accO[mi][nj2], pah[mi], vbh[nj2]);
                    mma16816(accO[mi][nj2], pah[mi], vbl[nj2]);
                    mma16816(accO[mi][nj2], pal[mi], vbh[nj2]);
                }
        }
    }

    // ---- cross-warp O reduction + normalize + split store to oS ----
    __syncthreads();
    float* Ob = (float*)smem;
    if (wn == 0) {
        #pragma unroll
        for (int mi = 0; mi < 2; mi++)
            #pragma unroll
            for (int hh = 0; hh < 2; hh++) {
                int r = wm * 32 + mi * 16 + hh * 8 + g;
                #pragma unroll
                for (int nj2 = 0; nj2 < 4; nj2++) {
                    Ob[r * 36 + nj2 * 8 + tg * 2]     = accO[mi][nj2][hh * 2];
                    Ob[r * 36 + nj2 * 8 + tg * 2 + 1] = accO[mi][nj2][hh * 2 + 1];
                }
            }
    }
    __syncthreads();
    if (wn == 1) {
        #pragma unroll
        for (int mi = 0; mi < 2; mi++)
            #pragma unroll
            for (int hh = 0; hh < 2; hh++) {
                int r = wm * 32 + mi * 16 + hh * 8 + g;
                float inv = 1.f / l_run[mi][hh];
                #pragma unroll
                for (int nj2 = 0; nj2 < 4; nj2++) {
                    int d = nj2 * 8 + tg * 2;
                    float v0 = (Ob[r * 36 + d]     + accO[mi][nj2][hh * 2])     * inv;
                    float v1 = (Ob[r * 36 + d + 1] + accO[mi][nj2][hh * 2 + 1]) * inv;
                    __nv_bfloat16 h0, l0, h1, l1;
                    split3(v0, h0, l0);
                    split3(v1, h1, l1);
                    long long base = (long long)(b * 1024 + q0 + r) * 768 + h * 32 + d;
                    oS[base]       = h0;  oS[base + 1]       = h1;
                    oS[base + 256] = h0;  oS[base + 256 + 1] = h1;
                    oS[base + 512] = l0;  oS[base + 512 + 1] = l1;
                }
            }
    }
}

// ======================= depthwise conv + SiLU, fused split outputs =======================
__global__ void __launch_bounds__(256) conv_silu_kernel(
    const float* __restrict__ xzy,
    const float* __restrict__ wx, const float* __restrict__ wz, const float* __restrict__ wy,
    float* __restrict__ xc, __nv_bfloat16* __restrict__ xcS,
    __nv_bfloat16* __restrict__ catS, __nv_bfloat16* __restrict__ ycS)
{
    int idx = blockIdx.x * 256 + threadIdx.x;
    int d = idx & 255;
    int m = idx >> 8;
    int l = m & 1023;
    const float* base = xzy + (long long)m * 768;
    float a0 = 0.f, a1 = 0.f, a2 = 0.f;
    #pragma unroll
    for (int k = 0; k < 4; k++) {
        int li = l + k - 1;
        if (li < 0 || li >= 1024) continue;
        const float* row = base + (long long)(k - 1) * 768;
        a0 = fmaf(row[d],       wx[d * 4 + k], a0);
        a1 = fmaf(row[256 + d], wz[d * 4 + k], a1);
        a2 = fmaf(row[512 + d], wy[d * 4 + k], a2);
    }
    a0 = a0 / (1.f + __expf(-a0));
    a1 = a1 / (1.f + __expf(-a1));
    a2 = a2 / (1.f + __expf(-a2));
    xc[idx] = a0;                              // fp32 for the scan
    __nv_bfloat16 hi, lo;
    split3(a0, hi, lo);                        // xcS modeA (stride 768)
    xcS[(long long)m * 768 + d] = hi;
    xcS[(long long)m * 768 + 256 + d] = hi;
    xcS[(long long)m * 768 + 512 + d] = lo;
    split3(a1, hi, lo);                        // z -> catS cols [256,512) modeA (stride 2304)
    catS[(long long)m * 2304 + 256 + d] = hi;
    catS[(long long)m * 2304 + 768 + 256 + d] = hi;
    catS[(long long)m * 2304 + 1536 + 256 + d] = lo;
    split3(a2, hi, lo);                        // ycS modeA
    ycS[(long long)m * 768 + d] = hi;
    ycS[(long long)m * 768 + 256 + d] = hi;
    ycS[(long long)m * 768 + 512 + d] = lo;
}

// ======================= selective scan (writes split into catS cols [0,256)) =======================
__global__ void __launch_bounds__(256) scan_kernel(
    const float* __restrict__ delta, const float* __restrict__ xc,
    const float* __restrict__ xdbl, const float* __restrict__ A_log,
    const float* __restrict__ D_param, __nv_bfloat16* __restrict__ catS)
{
    int t = blockIdx.x * 256 + threadIdx.x;
    int lane = t & 15;
    int p = t >> 4;
    int b = p >> 8;
    int d = p & 255;
    float Acoef = -__expf(A_log[d * 16 + lane]);
    float Dd = D_param[d];
    float h = 0.f;
    const float* dptr = delta + (long long)b * 1024 * 256 + d;
    const float* xptr = xc    + (long long)b * 1024 * 256 + d;
    const float* bptr = xdbl  + (long long)b * 1024 * 80 + 48 + lane;
    const float* cptr = bptr + 16;
    __nv_bfloat16* optr = catS + (long long)b * 1024 * 2304 + d;
    #pragma unroll 4
    for (int l = 0; l < 1024; l++) {
        float dl = dptr[(long long)l * 256];
        float xv = xptr[(long long)l * 256];
        float Bv = bptr[(long long)l * 80];
        float Cv = cptr[(long long)l * 80];
        float dA = __expf(dl * Acoef);
        h = fmaf(dA, h, dl * xv * Bv);
        float yv = h * Cv;
        yv += __shfl_xor_sync(0xffffffffu, yv, 1);
        yv += __shfl_xor_sync(0xffffffffu, yv, 2);
        yv += __shfl_xor_sync(0xffffffffu, yv, 4);
        yv += __shfl_xor_sync(0xffffffffu, yv, 8);
        if (lane == 0) {
            float v = fmaf(xv, Dd, yv);
            __nv_bfloat16 hi, lo;
            split3(v, hi, lo);
            optr[(long long)l * 2304] = hi;
            optr[(long long)l * 2304 + 768] = hi;
            optr[(long long)l * 2304 + 1536] = lo;
        }
    }
}

// ======================= host launcher =======================
extern "C" void kernel_launch(void* const* d_in, const int* in_sizes, int n_in,
                              void* d_out, int out_size)
{
    const float* hs          = (const float*)d_in[0];
    const float* in_proj_w   = (const float*)d_in[1];
    const float* conv_wx     = (const float*)d_in[2];
    const float* conv_wz     = (const float*)d_in[3];
    const float* conv_wy     = (const float*)d_in[4];
    const float* x_proj_w    = (const float*)d_in[5];
    const float* dt_proj_w   = (const float*)d_in[6];
    const float* dt_proj_b   = (const float*)d_in[7];
    const float* A_log       = (const float*)d_in[8];
    const float* D_param     = (const float*)d_in[9];
    const float* out_proj_w  = (const float*)d_in[10];
    const float* qkv_w       = (const float*)d_in[11];
    const float* attn_proj_w = (const float*)d_in[12];
    const float* attn_proj_b = (const float*)d_in[13];
    float* out = (float*)d_out;

    float *xzy, *xc, *xdbl, *delta, *qkv;
    cudaGetSymbolAddress((void**)&xzy,   g_xzy);
    cudaGetSymbolAddress((void**)&xc,    g_xc);
    cudaGetSymbolAddress((void**)&xdbl,  g_xdbl);
    cudaGetSymbolAddress((void**)&delta, g_delta);
    cudaGetSymbolAddress((void**)&qkv,   g_qkv);

    __nv_bfloat16 *hsS, *winS, *xcS, *wxpS, *dtS, *wdtS, *ycS, *wqkvS;
    __nv_bfloat16 *oS, *watS, *catS, *woutS;
    cudaGetSymbolAddress((void**)&hsS,   g_hsS);
    cudaGetSymbolAddress((void**)&winS,  g_winS);
    cudaGetSymbolAddress((void**)&xcS,   g_xcS);
    cudaGetSymbolAddress((void**)&wxpS,  g_wxpS);
    cudaGetSymbolAddress((void**)&dtS,   g_dtS);
    cudaGetSymbolAddress((void**)&wdtS,  g_wdtS);
    cudaGetSymbolAddress((void**)&ycS,   g_ycS);
    cudaGetSymbolAddress((void**)&wqkvS, g_wqkvS);
    cudaGetSymbolAddress((void**)&oS,    g_oS);
    cudaGetSymbolAddress((void**)&watS,  g_watS);
    cudaGetSymbolAddress((void**)&catS,  g_catS);
    cudaGetSymbolAddress((void**)&woutS, g_woutS);

    // 1) in_proj: xzy = hs @ in_proj_w^T   (4096x768, Kp=2304)
    split_kernel<<<12288, 256>>>(hs, 768, 4096, 768, hsS, 0);
    split_kernel<<<2304, 256>>>(in_proj_w, 768, 768, 768, winS, 1);
    gemm_mma<<<dim3(12, 32), 256>>>(hsS, winS, xzy, 4096, 768, 2304,
        2304, 2304, 768, 0, nullptr, 0.f, 1.f, 0, 0, 0);

    // 2) depthwise conv + SiLU (fused split outputs)
    conv_silu_kernel<<<4096, 256>>>(xzy, conv_wx, conv_wz, conv_wy, xc, xcS, catS, ycS);

    // 3) x_dbl = xc @ x_proj_w^T   (4096x80, Kp=768)
    split_kernel<<<80, 256>>>(x_proj_w, 256, 80, 256, wxpS, 1);
    gemm_mma<<<dim3(2, 32), 256>>>(xcS, wxpS, xdbl, 4096, 80, 768,
        768, 768, 80, 0, nullptr, 0.f, 1.f, 0, 0, 0);

    // 4) delta = softplus(dt @ dt_proj_w^T + 2*dt_proj_b)   (Kp=144)
    split_kernel<<<768, 256>>>(xdbl, 80, 4096, 48, dtS, 0);
    split_kernel<<<48, 256>>>(dt_proj_w, 48, 256, 48, wdtS, 1);
    gemm_mma<<<dim3(4, 32), 256>>>(dtS, wdtS, delta, 4096, 256, 144,
        144, 144, 256, 0, dt_proj_b, 2.f, 1.f, 2, 0, 0);

    // 5) selective scan -> catS cols [0,256) (split)
    scan_kernel<<<64, 256>>>(delta, xc, xdbl, A_log, D_param, catS);

    // 6) qkv = yc @ qkv_w^T   (4096x768, Kp=768)
    split_kernel<<<768, 256>>>(qkv_w, 256, 768, 256, wqkvS, 1);
    gemm_mma<<<dim3(12, 32), 256>>>(ycS, wqkvS, qkv, 4096, 768, 768,
        768, 768, 768, 0, nullptr, 0.f, 1.f, 0, 0, 0);

    // 7) fused flash attention -> oS (split, 4096x[3x256])
    flash_kernel<<<dim3(8, 32), 256>>>(qkv, oS);

    // 8) y_att = o @ attn_proj_w^T + b -> catS cols [512,768) (split epilogue)
    split_kernel<<<256, 256>>>(attn_proj_w, 256, 256, 256, watS, 1);
    gemm_mma<<<dim3(4, 32), 256>>>(oS, watS, (float*)catS, 4096, 256, 768,
        768, 768, 2304, 512, attn_proj_b, 1.f, 1.f, 1, 1, 768);

    // 9) out = catS @ out_proj_w^T   (Kp=2304)
    split_kernel<<<2304, 256>>>(out_proj_w, 768, 768, 768, woutS, 1);
    gemm_mma<<<dim3(12, 32), 256>>>(catS, woutS, out, 4096, 768, 2304,
        2304, 2304, 768, 0, nullptr, 0.f, 1.f, 0, 0, 0);
}

// round 7
// speedup vs baseline: 1.1645x; 1.0649x over previous
#include <cuda_runtime.h>
#include <cuda_bf16.h>
#include <math.h>
#include <stdint.h>

// Problem constants: B=4, L=1024, DM=768, DC=256, N=16, R=48, K=4, H=8, HD=32

// ======================= scratch buffers (static; no allocation) =======================
__device__ float g_xzy[4096 * 768];
__device__ float g_xc[4096 * 256];
__device__ float g_xdbl[4096 * 80];
__device__ float g_delta[4096 * 256];
__device__ float g_qkv[4096 * 768];

__device__ __nv_bfloat16 g_hsS[4096 * 2304];
__device__ __nv_bfloat16 g_winS[768 * 2304];
__device__ __nv_bfloat16 g_xcS[4096 * 768];
__device__ __nv_bfloat16 g_wxpS[80 * 768];
__device__ __nv_bfloat16 g_dtS[4096 * 144];
__device__ __nv_bfloat16 g_wdtS[256 * 144];
__device__ __nv_bfloat16 g_ycS[4096 * 768];
__device__ __nv_bfloat16 g_wqkvS[768 * 768];
__device__ __nv_bfloat16 g_oS[4096 * 768];
__device__ __nv_bfloat16 g_watS[256 * 768];
__device__ __nv_bfloat16 g_catS[4096 * 2304];
__device__ __nv_bfloat16 g_woutS[768 * 2304];

// ======================= small asm helpers =======================
__device__ __forceinline__ uint32_t smem_to_u32(const void* smem_ptr) {
    uint32_t addr;
    asm("{ .reg .u64 tmp; cvta.to.shared.u64 tmp, %1; cvt.u32.u64 %0, tmp; }"
        : "=r"(addr) : "l"(smem_ptr));
    return addr;
}

__device__ __forceinline__ uint32_t lds32(uint32_t a) {
    uint32_t v;
    asm volatile("ld.shared.b32 %0, [%1];" : "=r"(v) : "r"(a));
    return v;
}

__device__ __forceinline__ void ldsm4(uint32_t* r, uint32_t a) {
    asm volatile("ldmatrix.sync.aligned.m8n8.x4.shared.b16 {%0,%1,%2,%3}, [%4];"
                 : "=r"(r[0]), "=r"(r[1]), "=r"(r[2]), "=r"(r[3]) : "r"(a));
}

__device__ __forceinline__ void cp16(uint32_t dst, const void* src, bool pred) {
    int sz = pred ? 16 : 0;
    asm volatile("cp.async.cg.shared.global [%0], [%1], 16, %2;"
                 :: "r"(dst), "l"(src), "r"(sz) : "memory");
}

__device__ __forceinline__ void mma16816(float* c, const uint32_t* a, const uint32_t* b) {
    asm volatile(
        "mma.sync.aligned.m16n8k16.row.col.f32.bf16.bf16.f32 "
        "{%0,%1,%2,%3}, {%4,%5,%6,%7}, {%8,%9}, {%0,%1,%2,%3};"
        : "+f"(c[0]), "+f"(c[1]), "+f"(c[2]), "+f"(c[3])
        : "r"(a[0]), "r"(a[1]), "r"(a[2]), "r"(a[3]), "r"(b[0]), "r"(b[1]));
}

__device__ __forceinline__ uint32_t packh(float x, float y) {
    __nv_bfloat162 t = __floats2bfloat162_rn(x, y);
    return *(uint32_t*)&t;
}

__device__ __forceinline__ void split3(float f, __nv_bfloat16& hi, __nv_bfloat16& lo) {
    hi = __float2bfloat16(f);
    lo = __float2bfloat16(f - __bfloat162float(hi));
}

// ======================= split-bf16 conversion (generic, modeA/modeB) =======================
__global__ void __launch_bounds__(256) split_kernel(
    const float* __restrict__ src, int ld,
    int M, int K, __nv_bfloat16* __restrict__ dst, int modeB)
{
    int idx = blockIdx.x * 256 + threadIdx.x;
    if (idx >= M * K) return;
    int m = idx / K, k = idx - m * K;
    float f = src[(long long)m * ld + k];
    __nv_bfloat16 hi, lo;
    split3(f, hi, lo);
    __nv_bfloat16* r = dst + (long long)m * 3 * K;
    if (modeB) { r[k] = hi; r[K + k] = lo; r[2 * K + k] = hi; }
    else       { r[k] = hi; r[K + k] = hi; r[2 * K + k] = lo; }
}

// ======================= merged weight splits (all modeB, ld==K contiguous) ==================
__global__ void __launch_bounds__(256) weight_split_kernel(
    const float* __restrict__ w_in, const float* __restrict__ w_xp,
    const float* __restrict__ w_dt, const float* __restrict__ w_qkv,
    const float* __restrict__ w_at, const float* __restrict__ w_out,
    __nv_bfloat16* __restrict__ winS, __nv_bfloat16* __restrict__ wxpS,
    __nv_bfloat16* __restrict__ wdtS, __nv_bfloat16* __restrict__ wqkvS,
    __nv_bfloat16* __restrict__ watS, __nv_bfloat16* __restrict__ woutS)
{
    int idx = blockIdx.x * 256 + threadIdx.x;
    const float* src; __nv_bfloat16* dst; int K;
    int rem = idx;
    if (rem < 589824)                 { src = w_in;  dst = winS;  K = 768; }
    else if ((rem -= 589824) < 20480) { src = w_xp;  dst = wxpS;  K = 256; }
    else if ((rem -= 20480) < 12288)  { src = w_dt;  dst = wdtS;  K = 48;  }
    else if ((rem -= 12288) < 196608) { src = w_qkv; dst = wqkvS; K = 256; }
    else if ((rem -= 196608) < 65536) { src = w_at;  dst = watS;  K = 256; }
    else                              { rem -= 65536; src = w_out; dst = woutS; K = 768; }
    int m = rem / K, k = rem - m * K;
    float f = src[(long long)m * K + k];
    __nv_bfloat16 hi, lo;
    split3(f, hi, lo);
    __nv_bfloat16* r = dst + (long long)m * 3 * K;
    r[k] = hi; r[K + k] = lo; r[2 * K + k] = hi;
}

// ======================= HMMA bf16 NT GEMM, 128x64x32, 3-stage + ldmatrix =======================
// epi: 0 none, 1 +bias*bscale, 2 softplus(v + bias*bscale)
// osplit: C is bf16; write modeA triplet [hi,hi,lo] at coff+c, +Kof, +2*Kof.
// dual: if splitx>0 and blockIdx.x>=splitx, switch to (A2,B2,C2,N2,ldc2) (epi=0 path).
#define ASTR 80
#define STG 15360      // 128*80 (A) + 64*80 (B)
__global__ void __launch_bounds__(256, 3) gemm_mma(
    const __nv_bfloat16* __restrict__ A, const __nv_bfloat16* __restrict__ B,
    float* __restrict__ C, int M, int Nglob, int Kp,
    int lda, int ldb, int ldc, int coff,
    const float* __restrict__ bias, float bscale, float alpha, int epi,
    int osplit, int Kof,
    const __nv_bfloat16* __restrict__ A2, const __nv_bfloat16* __restrict__ B2,
    float* __restrict__ C2, int N2, int ldc2, int splitx)
{
    __shared__ __align__(16) char smem[3 * STG];
    uint32_t sb = smem_to_u32(smem);
    int tid = threadIdx.x;
    int bx = blockIdx.x;
    int n0;
    if (splitx && bx >= splitx) {
        A = A2; B = B2; C = C2; Nglob = N2; ldc = ldc2;
        epi = 0; osplit = 0; coff = 0;
        n0 = (bx - splitx) * 64;
    } else {
        n0 = bx * 64;
    }
    int m0 = blockIdx.y * 128;
    int NC = (Kp + 31) >> 5;

    auto load_stage = [&](int c) {
        int k0 = c * 32;
        uint32_t ab = sb + (c % 3) * STG;
        uint32_t bb = ab + 10240;
        #pragma unroll
        for (int i = 0; i < 2; i++) {
            int gg = tid + i * 256;
            int r = gg >> 2, c16 = gg & 3;
            int k = k0 + c16 * 8;
            cp16(ab + r * ASTR + c16 * 16, A + (long long)(m0 + r) * lda + k, k < Kp);
        }
        {
            int r = tid >> 2, c16 = tid & 3;
            int k = k0 + c16 * 8;
            cp16(bb + r * ASTR + c16 * 16, B + (long long)(n0 + r) * ldb + k,
                 (n0 + r) < Nglob && k < Kp);
        }
        asm volatile("cp.async.commit_group;" ::: "memory");
    };

    int wid = tid >> 5, lane = tid & 31;
    int wm = wid & 3, wn = wid >> 2;          // 4x2 warps, warp tile 32x32
    int g = lane >> 2, tg = lane & 3;
    int l7 = lane & 7;

    // ldmatrix lane-address offsets (stage-relative, add ks*32)
    uint32_t aoff0 = (uint32_t)((wm * 32 + l7 + ((lane >> 3) & 1) * 8) * ASTR + (lane >> 4) * 16);
    uint32_t aoff1 = aoff0 + 16 * ASTR;
    uint32_t boff0 = (uint32_t)((wn * 32 + (lane >> 4) * 8 + l7) * ASTR + ((lane >> 3) & 1) * 16);
    uint32_t boff1 = boff0 + 16 * ASTR;

    float acc[2][4][4] = {};

    load_stage(0);
    if (1 < NC) load_stage(1);

    for (int c = 0; c < NC; c++) {
        if (c + 1 < NC) { asm volatile("cp.async.wait_group 1;" ::: "memory"); }
        else            { asm volatile("cp.async.wait_group 0;" ::: "memory"); }
        __syncthreads();
        if (c + 2 < NC) load_stage(c + 2);

        uint32_t ab = sb + (c % 3) * STG;
        uint32_t bb = ab + 10240;
        #pragma unroll
        for (int ks = 0; ks < 2; ks++) {
            uint32_t a0[4], a1[4], b0[4], b1[4];
            ldsm4(a0, ab + aoff0 + ks * 32);
            ldsm4(a1, ab + aoff1 + ks * 32);
            ldsm4(b0, bb + boff0 + ks * 32);
            ldsm4(b1, bb + boff1 + ks * 32);
            mma16816(acc[0][0], a0, b0 + 0);
            mma16816(acc[0][1], a0, b0 + 2);
            mma16816(acc[0][2], a0, b1 + 0);
            mma16816(acc[0][3], a0, b1 + 2);
            mma16816(acc[1][0], a1, b0 + 0);
            mma16816(acc[1][1], a1, b0 + 2);
            mma16816(acc[1][2], a1, b1 + 0);
            mma16816(acc[1][3], a1, b1 + 2);
        }
    }
    __syncthreads();

    // ---- epilogue ----
    #pragma unroll
    for (int mi = 0; mi < 2; mi++) {
        int r0 = m0 + wm * 32 + mi * 16 + g;
        #pragma unroll
        for (int nj = 0; nj < 4; nj++) {
            int cc = n0 + wn * 32 + nj * 8 + tg * 2;
            if (cc >= Nglob) continue;
            #pragma unroll
            for (int hh = 0; hh < 2; hh++) {
                int rr = r0 + hh * 8;
                float v0 = acc[mi][nj][hh * 2 + 0] * alpha;
                float v1 = acc[mi][nj][hh * 2 + 1] * alpha;
                if (epi >= 1) { v0 += bias[cc] * bscale; v1 += bias[cc + 1] * bscale; }
                if (epi == 2) {
                    v0 = (v0 > 15.f) ? v0 : log1pf(__expf(v0));
                    v1 = (v1 > 15.f) ? v1 : log1pf(__expf(v1));
                }
                if (!osplit) {
                    *(float2*)&C[(long long)rr * ldc + coff + cc] = make_float2(v0, v1);
                } else {
                    __nv_bfloat16* Cb = (__nv_bfloat16*)C;
                    long long base = (long long)rr * ldc + coff + cc;
                    __nv_bfloat16 h0, l0, h1, l1;
                    split3(v0, h0, l0);
                    split3(v1, h1, l1);
                    Cb[base]           = h0;  Cb[base + 1]           = h1;
                    Cb[base + Kof]     = h0;  Cb[base + Kof + 1]     = h1;
                    Cb[base + 2 * Kof] = l0;  Cb[base + 2 * Kof + 1] = l1;
                }
            }
        }
    }
}

// ======================= fused flash attention (writes split-bf16 oS) =======================
#define SQ 208
#define SV 272
#define OFF_VTH 26624
#define OFF_VTL 35328
#define OFF_RMAX 44032
#define OFF_RSUM 45056
__global__ void __launch_bounds__(256, 1) flash_kernel(
    const float* __restrict__ qkv, __nv_bfloat16* __restrict__ oS)
{
    __shared__ __align__(16) char smem[46080];
    uint32_t sb = smem_to_u32(smem);
    float* rmax = (float*)(smem + OFF_RMAX);
    float* rsum = (float*)(smem + OFF_RSUM);
    int tid = threadIdx.x;
    int wid = tid >> 5, lane = tid & 31;
    int wm = wid & 3, wn = wid >> 2;
    int g = lane >> 2, tg = lane & 3;
    int z = blockIdx.y;
    int b = z >> 3, h = z & 7;
    int q0 = blockIdx.x * 128;
    const float alpha = 0.17677669529663687f;
    const float* qkvb = qkv + (long long)b * 1024 * 768 + h * 32;

    #pragma unroll
    for (int j = 0; j < 16; j++) {
        int i = tid + j * 256;
        int row = i >> 5, d = i & 31;
        float f = qkvb[(long long)(q0 + row) * 768 + d] * alpha;
        __nv_bfloat16 hi, lo;
        split3(f, hi, lo);
        *(__nv_bfloat16*)(smem + row * SQ + d * 2) = hi;
        *(__nv_bfloat16*)(smem + row * SQ + 64 + d * 2) = hi;
        *(__nv_bfloat16*)(smem + row * SQ + 128 + d * 2) = lo;
    }
    __syncthreads();
    uint32_t qa[6][2][4];
    #pragma unroll
    for (int kb = 0; kb < 6; kb++)
        #pragma unroll
        for (int mi = 0; mi < 2; mi++) {
            uint32_t base = sb + (wm * 32 + mi * 16 + g) * SQ + kb * 32 + tg * 4;
            qa[kb][mi][0] = lds32(base);
            qa[kb][mi][1] = lds32(base + 8 * SQ);
            qa[kb][mi][2] = lds32(base + 16);
            qa[kb][mi][3] = lds32(base + 8 * SQ + 16);
        }

    float accO[2][4][4] = {};
    float m_run[2][2] = {{-1e30f, -1e30f}, {-1e30f, -1e30f}};
    float l_run[2][2] = {{0.f, 0.f}, {0.f, 0.f}};

    for (int t = 0; t < 8; t++) {
        int j0 = t * 128;
        __syncthreads();
        #pragma unroll
        for (int j = 0; j < 16; j++) {
            int i = tid + j * 256;
            int key = i >> 5, d = i & 31;
            const float* src = qkvb + (long long)(j0 + key) * 768;
            float kf = src[256 + d];
            __nv_bfloat16 khi, klo;
            split3(kf, khi, klo);
            *(__nv_bfloat16*)(smem + key * SQ + d * 2) = khi;
            *(__nv_bfloat16*)(smem + key * SQ + 64 + d * 2) = klo;
            *(__nv_bfloat16*)(smem + key * SQ + 128 + d * 2) = khi;
            float vf = src[512 + d];
            __nv_bfloat16 vhi, vlo;
            split3(vf, vhi, vlo);
            *(__nv_bfloat16*)(smem + OFF_VTH + d * SV + key * 2) = vhi;
            *(__nv_bfloat16*)(smem + OFF_VTL + d * SV + key * 2) = vlo;
        }
        __syncthreads();

        float accS[2][8][4] = {};
        #pragma unroll
        for (int kb = 0; kb < 6; kb++) {
            uint32_t bfr[8][2];
            #pragma unroll
            for (int nj = 0; nj < 8; nj++) {
                uint32_t base = sb + (wn * 64 + nj * 8 + g) * SQ + kb * 32 + tg * 4;
                bfr[nj][0] = lds32(base);
                bfr[nj][1] = lds32(base + 16);
            }
            #pragma unroll
            for (int mi = 0; mi < 2; mi++)
                #pragma unroll
                for (int nj = 0; nj < 8; nj++)
                    mma16816(accS[mi][nj], qa[kb][mi], bfr[nj]);
        }

        float mx[2][2];
        #pragma unroll
        for (int mi = 0; mi < 2; mi++)
            #pragma unroll
            for (int hh = 0; hh < 2; hh++) {
                float m = -1e30f;
                #pragma unroll
                for (int nj = 0; nj < 8; nj++)
                    m = fmaxf(m, fmaxf(accS[mi][nj][hh * 2], accS[mi][nj][hh * 2 + 1]));
                m = fmaxf(m, __shfl_xor_sync(0xffffffffu, m, 1));
                m = fmaxf(m, __shfl_xor_sync(0xffffffffu, m, 2));
                mx[mi][hh] = m;
            }
        if (tg == 0) {
            #pragma unroll
            for (int mi = 0; mi < 2; mi++)
                #pragma unroll
                for (int hh = 0; hh < 2; hh++)
                    rmax[wn * 128 + wm * 32 + mi * 16 + hh * 8 + g] = mx[mi][hh];
        }
        __syncthreads();

        float fsc[2][2], mnew[2][2], ls[2][2];
        #pragma unroll
        for (int mi = 0; mi < 2; mi++)
            #pragma unroll
            for (int hh = 0; hh < 2; hh++) {
                int r = wm * 32 + mi * 16 + hh * 8 + g;
                float tm = fmaxf(rmax[r], rmax[128 + r]);
                float mn = fmaxf(m_run[mi][hh], tm);
                mnew[mi][hh] = mn;
                fsc[mi][hh] = __expf(m_run[mi][hh] - mn);
                ls[mi][hh] = 0.f;
            }
        #pragma unroll
        for (int mi = 0; mi < 2; mi++)
            #pragma unroll
            for (int hh = 0; hh < 2; hh++) {
                float mn = mnew[mi][hh];
                float s = 0.f;
                #pragma unroll
                for (int nj = 0; nj < 8; nj++) {
                    float p0 = __expf(accS[mi][nj][hh * 2] - mn);
                    float p1 = __expf(accS[mi][nj][hh * 2 + 1] - mn);
                    accS[mi][nj][hh * 2] = p0;
                    accS[mi][nj][hh * 2 + 1] = p1;
                    s += p0 + p1;
                }
                ls[mi][hh] = s;
                float f = fsc[mi][hh];
                #pragma unroll
                for (int nj2 = 0; nj2 < 4; nj2++) {
                    accO[mi][nj2][hh * 2] *= f;
                    accO[mi][nj2][hh * 2 + 1] *= f;
                }
            }
        #pragma unroll
        for (int mi = 0; mi < 2; mi++)
            #pragma unroll
            for (int hh = 0; hh < 2; hh++) {
                float s = ls[mi][hh];
                s += __shfl_xor_sync(0xffffffffu, s, 1);
                s += __shfl_xor_sync(0xffffffffu, s, 2);
                ls[mi][hh] = s;
            }
        if (tg == 0) {
            #pragma unroll
            for (int mi = 0; mi < 2; mi++)
                #pragma unroll
                for (int hh = 0; hh < 2; hh++)
                    rsum[wn * 128 + wm * 32 + mi * 16 + hh * 8 + g] = ls[mi][hh];
        }
        __syncthreads();
        #pragma unroll
        for (int mi = 0; mi < 2; mi++)
            #pragma unroll
            for (int hh = 0; hh < 2; hh++) {
                int r = wm * 32 + mi * 16 + hh * 8 + g;
                l_run[mi][hh] = l_run[mi][hh] * fsc[mi][hh] + rsum[r] + rsum[128 + r];
                m_run[mi][hh] = mnew[mi][hh];
            }

        #pragma unroll
        for (int kb = 0; kb < 4; kb++) {
            uint32_t pah[2][4], pal[2][4];
            #pragma unroll
            for (int mi = 0; mi < 2; mi++) {
                float x0 = accS[mi][2 * kb][0], x1 = accS[mi][2 * kb][1];
                float x2 = accS[mi][2 * kb][2], x3 = accS[mi][2 * kb][3];
                float y0 = accS[mi][2 * kb + 1][0], y1 = accS[mi][2 * kb + 1][1];
                float y2 = accS[mi][2 * kb + 1][2], y3 = accS[mi][2 * kb + 1][3];
                pah[mi][0] = packh(x0, x1);
                pah[mi][1] = packh(x2, x3);
                pah[mi][2] = packh(y0, y1);
                pah[mi][3] = packh(y2, y3);
                __nv_bfloat162 t0 = *(__nv_bfloat162*)&pah[mi][0];
                __nv_bfloat162 t1 = *(__nv_bfloat162*)&pah[mi][1];
                __nv_bfloat162 t2 = *(__nv_bfloat162*)&pah[mi][2];
                __nv_bfloat162 t3 = *(__nv_bfloat162*)&pah[mi][3];
                pal[mi][0] = packh(x0 - __bfloat162float(t0.x), x1 - __bfloat162float(t0.y));
                pal[mi][1] = packh(x2 - __bfloat162float(t1.x), x3 - __bfloat162float(t1.y));
                pal[mi][2] = packh(y0 - __bfloat162float(t2.x), y1 - __bfloat162float(t2.y));
                pal[mi][3] = packh(y2 - __bfloat162float(t3.x), y3 - __bfloat162float(t3.y));
            }
            uint32_t vbh[4][2], vbl[4][2];
            int kcol = (wn * 64 + kb * 16 + tg * 2) * 2;
            #pragma unroll
            for (int nj2 = 0; nj2 < 4; nj2++) {
                uint32_t bh = sb + OFF_VTH + (nj2 * 8 + g) * SV + kcol;
                uint32_t bl = sb + OFF_VTL + (nj2 * 8 + g) * SV + kcol;
                vbh[nj2][0] = lds32(bh);  vbh[nj2][1] = lds32(bh + 16);
                vbl[nj2][0] = lds32(bl);  vbl[nj2][1] = lds32(bl + 16);
            }
            #pragma unroll
            for (int mi = 0; mi < 2; mi++)
                #pragma unroll
                for (int nj2 = 0; nj2 < 4; nj2++) {
                    mma16816(accO[mi][nj2], pah[mi], vbh[nj2]);
                    mma16816(accO[mi][nj2], pah[mi], vbl[nj2]);
                    mma16816(accO[mi][nj2], pal[mi], vbh[nj2]);
                }
        }
    }

    // ---- cross-warp O reduction + normalize + split store to oS ----
    __syncthreads();
    float* Ob = (float*)smem;
    if (wn == 0) {
        #pragma unroll
        for (int mi = 0; mi < 2; mi++)
            #pragma unroll
            for (int hh = 0; hh < 2; hh++) {
                int r = wm * 32 + mi * 16 + hh * 8 + g;
                #pragma unroll
                for (int nj2 = 0; nj2 < 4; nj2++) {
                    Ob[r * 36 + nj2 * 8 + tg * 2]     = accO[mi][nj2][hh * 2];
                    Ob[r * 36 + nj2 * 8 + tg * 2 + 1] = accO[mi][nj2][hh * 2 + 1];
                }
            }
    }
    __syncthreads();
    if (wn == 1) {
        #pragma unroll
        for (int mi = 0; mi < 2; mi++)
            #pragma unroll
            for (int hh = 0; hh < 2; hh++) {
                int r = wm * 32 + mi * 16 + hh * 8 + g;
                float inv = 1.f / l_run[mi][hh];
                #pragma unroll
                for (int nj2 = 0; nj2 < 4; nj2++) {
                    int d = nj2 * 8 + tg * 2;
                    float v0 = (Ob[r * 36 + d]     + accO[mi][nj2][hh * 2])     * inv;
                    float v1 = (Ob[r * 36 + d + 1] + accO[mi][nj2][hh * 2 + 1]) * inv;
                    __nv_bfloat16 h0, l0, h1, l1;
                    split3(v0, h0, l0);
                    split3(v1, h1, l1);
                    long long base = (long long)(b * 1024 + q0 + r) * 768 + h * 32 + d;
                    oS[base]       = h0;  oS[base + 1]       = h1;
                    oS[base + 256] = h0;  oS[base + 256 + 1] = h1;
                    oS[base + 512] = l0;  oS[base + 512 + 1] = l1;
                }
            }
    }
}

// ======================= depthwise conv + SiLU, fused split outputs =======================
__global__ void __launch_bounds__(256) conv_silu_kernel(
    const float* __restrict__ xzy,
    const float* __restrict__ wx, const float* __restrict__ wz, const float* __restrict__ wy,
    float* __restrict__ xc, __nv_bfloat16* __restrict__ xcS,
    __nv_bfloat16* __restrict__ catS, __nv_bfloat16* __restrict__ ycS)
{
    int idx = blockIdx.x * 256 + threadIdx.x;
    int d = idx & 255;
    int m = idx >> 8;
    int l = m & 1023;
    const float* base = xzy + (long long)m * 768;
    float a0 = 0.f, a1 = 0.f, a2 = 0.f;
    #pragma unroll
    for (int k = 0; k < 4; k++) {
        int li = l + k - 1;
        if (li < 0 || li >= 1024) continue;
        const float* row = base + (long long)(k - 1) * 768;
        a0 = fmaf(row[d],       wx[d * 4 + k], a0);
        a1 = fmaf(row[256 + d], wz[d * 4 + k], a1);
        a2 = fmaf(row[512 + d], wy[d * 4 + k], a2);
    }
    a0 = a0 / (1.f + __expf(-a0));
    a1 = a1 / (1.f + __expf(-a1));
    a2 = a2 / (1.f + __expf(-a2));
    xc[idx] = a0;
    __nv_bfloat16 hi, lo;
    split3(a0, hi, lo);
    xcS[(long long)m * 768 + d] = hi;
    xcS[(long long)m * 768 + 256 + d] = hi;
    xcS[(long long)m * 768 + 512 + d] = lo;
    split3(a1, hi, lo);
    catS[(long long)m * 2304 + 256 + d] = hi;
    catS[(long long)m * 2304 + 768 + 256 + d] = hi;
    catS[(long long)m * 2304 + 1536 + 256 + d] = lo;
    split3(a2, hi, lo);
    ycS[(long long)m * 768 + d] = hi;
    ycS[(long long)m * 768 + 256 + d] = hi;
    ycS[(long long)m * 768 + 512 + d] = lo;
}

// ======================= selective scan (writes split into catS cols [0,256)) =======================
__global__ void __launch_bounds__(256) scan_kernel(
    const float* __restrict__ delta, const float* __restrict__ xc,
    const float* __restrict__ xdbl, const float* __restrict__ A_log,
    const float* __restrict__ D_param, __nv_bfloat16* __restrict__ catS)
{
    int t = blockIdx.x * 256 + threadIdx.x;
    int lane = t & 15;
    int p = t >> 4;
    int b = p >> 8;
    int d = p & 255;
    float Acoef = -__expf(A_log[d * 16 + lane]);
    float Dd = D_param[d];
    float h = 0.f;
    const float* dptr = delta + (long long)b * 1024 * 256 + d;
    const float* xptr = xc    + (long long)b * 1024 * 256 + d;
    const float* bptr = xdbl  + (long long)b * 1024 * 80 + 48 + lane;
    const float* cptr = bptr + 16;
    __nv_bfloat16* optr = catS + (long long)b * 1024 * 2304 + d;
    #pragma unroll 4
    for (int l = 0; l < 1024; l++) {
        float dl = dptr[(long long)l * 256];
        float xv = xptr[(long long)l * 256];
        float Bv = bptr[(long long)l * 80];
        float Cv = cptr[(long long)l * 80];
        float dA = __expf(dl * Acoef);
        h = fmaf(dA, h, dl * xv * Bv);
        float yv = h * Cv;
        yv += __shfl_xor_sync(0xffffffffu, yv, 1);
        yv += __shfl_xor_sync(0xffffffffu, yv, 2);
        yv += __shfl_xor_sync(0xffffffffu, yv, 4);
        yv += __shfl_xor_sync(0xffffffffu, yv, 8);
        if (lane == 0) {
            float v = fmaf(xv, Dd, yv);
            __nv_bfloat16 hi, lo;
            split3(v, hi, lo);
            optr[(long long)l * 2304] = hi;
            optr[(long long)l * 2304 + 768] = hi;
            optr[(long long)l * 2304 + 1536] = lo;
        }
    }
}

// ======================= host launcher =======================
extern "C" void kernel_launch(void* const* d_in, const int* in_sizes, int n_in,
                              void* d_out, int out_size)
{
    const float* hs          = (const float*)d_in[0];
    const float* in_proj_w   = (const float*)d_in[1];
    const float* conv_wx     = (const float*)d_in[2];
    const float* conv_wz     = (const float*)d_in[3];
    const float* conv_wy     = (const float*)d_in[4];
    const float* x_proj_w    = (const float*)d_in[5];
    const float* dt_proj_w   = (const float*)d_in[6];
    const float* dt_proj_b   = (const float*)d_in[7];
    const float* A_log       = (const float*)d_in[8];
    const float* D_param     = (const float*)d_in[9];
    const float* out_proj_w  = (const float*)d_in[10];
    const float* qkv_w       = (const float*)d_in[11];
    const float* attn_proj_w = (const float*)d_in[12];
    const float* attn_proj_b = (const float*)d_in[13];
    float* out = (float*)d_out;

    float *xzy, *xc, *xdbl, *delta, *qkv;
    cudaGetSymbolAddress((void**)&xzy,   g_xzy);
    cudaGetSymbolAddress((void**)&xc,    g_xc);
    cudaGetSymbolAddress((void**)&xdbl,  g_xdbl);
    cudaGetSymbolAddress((void**)&delta, g_delta);
    cudaGetSymbolAddress((void**)&qkv,   g_qkv);

    __nv_bfloat16 *hsS, *winS, *xcS, *wxpS, *dtS, *wdtS, *ycS, *wqkvS;
    __nv_bfloat16 *oS, *watS, *catS, *woutS;
    cudaGetSymbolAddress((void**)&hsS,   g_hsS);
    cudaGetSymbolAddress((void**)&winS,  g_winS);
    cudaGetSymbolAddress((void**)&xcS,   g_xcS);
    cudaGetSymbolAddress((void**)&wxpS,  g_wxpS);
    cudaGetSymbolAddress((void**)&dtS,   g_dtS);
    cudaGetSymbolAddress((void**)&wdtS,  g_wdtS);
    cudaGetSymbolAddress((void**)&ycS,   g_ycS);
    cudaGetSymbolAddress((void**)&wqkvS, g_wqkvS);
    cudaGetSymbolAddress((void**)&oS,    g_oS);
    cudaGetSymbolAddress((void**)&watS,  g_watS);
    cudaGetSymbolAddress((void**)&catS,  g_catS);
    cudaGetSymbolAddress((void**)&woutS, g_woutS);

    // 1) input + all-weight splits
    split_kernel<<<12288, 256>>>(hs, 768, 4096, 768, hsS, 0);
    weight_split_kernel<<<5760, 256>>>(in_proj_w, x_proj_w, dt_proj_w, qkv_w,
        attn_proj_w, out_proj_w, winS, wxpS, wdtS, wqkvS, watS, woutS);

    // 2) in_proj: xzy = hs @ in_proj_w^T   (Kp=2304)
    gemm_mma<<<dim3(12, 32), 256>>>(hsS, winS, xzy, 4096, 768, 2304,
        2304, 2304, 768, 0, nullptr, 0.f, 1.f, 0, 0, 0,
        nullptr, nullptr, nullptr, 0, 0, 0);

    // 3) depthwise conv + SiLU (fused split outputs)
    conv_silu_kernel<<<4096, 256>>>(xzy, conv_wx, conv_wz, conv_wy, xc, xcS, catS, ycS);

    // 4) DUAL: qkv = yc @ qkv_w^T (bx<12)  ‖  x_dbl = xc @ x_proj_w^T (bx>=12)   (Kp=768)
    gemm_mma<<<dim3(14, 32), 256>>>(ycS, wqkvS, qkv, 4096, 768, 768,
        768, 768, 768, 0, nullptr, 0.f, 1.f, 0, 0, 0,
        xcS, wxpS, xdbl, 80, 80, 12);

    // 5) fused flash attention -> oS (split)
    flash_kernel<<<dim3(8, 32), 256>>>(qkv, oS);

    // 6) dt split + delta = softplus(dt @ dt_proj_w^T + 2*b)   (Kp=144)
    split_kernel<<<768, 256>>>(xdbl, 80, 4096, 48, dtS, 0);
    gemm_mma<<<dim3(4, 32), 256>>>(dtS, wdtS, delta, 4096, 256, 144,
        144, 144, 256, 0, dt_proj_b, 2.f, 1.f, 2, 0, 0,
        nullptr, nullptr, nullptr, 0, 0, 0);

    // 7) selective scan -> catS cols [0,256) (split)
    scan_kernel<<<64, 256>>>(delta, xc, xdbl, A_log, D_param, catS);

    // 8) y_att = o @ attn_proj_w^T + b -> catS cols [512,768) (split epilogue)
    gemm_mma<<<dim3(4, 32), 256>>>(oS, watS, (float*)catS, 4096, 256, 768,
        768, 768, 2304, 512, attn_proj_b, 1.f, 1.f, 1, 1, 768,
        nullptr, nullptr, nullptr, 0, 0, 0);

    // 9) out = catS @ out_proj_w^T   (Kp=2304)
    gemm_mma<<<dim3(12, 32), 256>>>(catS, woutS, out, 4096, 768, 2304,
        2304, 2304, 768, 0, nullptr, 0.f, 1.f, 0, 0, 0,
        nullptr, nullptr, nullptr, 0, 0, 0);
}

// round 9
// speedup vs baseline: 1.2531x; 1.0761x over previous
#include <cuda_runtime.h>
#include <cuda_bf16.h>
#include <math.h>
#include <stdint.h>

// Problem constants: B=4, L=1024, DM=768, DC=256, N=16, R=48, K=4, H=8, HD=32
// Split-2 storage: every GEMM operand stored as [hi(K) | lo(K)] bf16, 2K wide.
// GEMM computes C = Ah*Bh + Ah*Bl + Al*Bh (3 MMA passes per k-step).

// ======================= scratch buffers (static; no allocation) =======================
__device__ float g_xzy[4096 * 768];
__device__ float g_xc[4096 * 256];
__device__ float g_xdbl[4096 * 80];
__device__ float g_delta[4096 * 256];
__device__ float g_qkv[4096 * 768];

__device__ __nv_bfloat16 g_hsS[4096 * 1536];
__device__ __nv_bfloat16 g_winS[768 * 1536];
__device__ __nv_bfloat16 g_xcS[4096 * 512];
__device__ __nv_bfloat16 g_wxpS[80 * 512];
__device__ __nv_bfloat16 g_dtS[4096 * 96];
__device__ __nv_bfloat16 g_wdtS[256 * 96];
__device__ __nv_bfloat16 g_ycS[4096 * 512];
__device__ __nv_bfloat16 g_wqkvS[768 * 512];
__device__ __nv_bfloat16 g_oS[4096 * 512];
__device__ __nv_bfloat16 g_watS[256 * 512];
__device__ __nv_bfloat16 g_catS[4096 * 1536];
__device__ __nv_bfloat16 g_woutS[768 * 1536];

// ======================= small asm helpers =======================
__device__ __forceinline__ uint32_t smem_to_u32(const void* smem_ptr) {
    uint32_t addr;
    asm("{ .reg .u64 tmp; cvta.to.shared.u64 tmp, %1; cvt.u32.u64 %0, tmp; }"
        : "=r"(addr) : "l"(smem_ptr));
    return addr;
}

__device__ __forceinline__ uint32_t lds32(uint32_t a) {
    uint32_t v;
    asm volatile("ld.shared.b32 %0, [%1];" : "=r"(v) : "r"(a));
    return v;
}

__device__ __forceinline__ void ldsm4(uint32_t* r, uint32_t a) {
    asm volatile("ldmatrix.sync.aligned.m8n8.x4.shared.b16 {%0,%1,%2,%3}, [%4];"
                 : "=r"(r[0]), "=r"(r[1]), "=r"(r[2]), "=r"(r[3]) : "r"(a));
}

__device__ __forceinline__ void cp16(uint32_t dst, const void* src, bool pred) {
    int sz = pred ? 16 : 0;
    asm volatile("cp.async.cg.shared.global [%0], [%1], 16, %2;"
                 :: "r"(dst), "l"(src), "r"(sz) : "memory");
}

__device__ __forceinline__ void mma16816(float* c, const uint32_t* a, const uint32_t* b) {
    asm volatile(
        "mma.sync.aligned.m16n8k16.row.col.f32.bf16.bf16.f32 "
        "{%0,%1,%2,%3}, {%4,%5,%6,%7}, {%8,%9}, {%0,%1,%2,%3};"
        : "+f"(c[0]), "+f"(c[1]), "+f"(c[2]), "+f"(c[3])
        : "r"(a[0]), "r"(a[1]), "r"(a[2]), "r"(a[3]), "r"(b[0]), "r"(b[1]));
}

__device__ __forceinline__ uint32_t packh(float x, float y) {
    __nv_bfloat162 t = __floats2bfloat162_rn(x, y);
    return *(uint32_t*)&t;
}

__device__ __forceinline__ void split3(float f, __nv_bfloat16& hi, __nv_bfloat16& lo) {
    hi = __float2bfloat16(f);
    lo = __float2bfloat16(f - __bfloat162float(hi));
}

// ======================= split-bf16 conversion, [hi|lo] layout =======================
__global__ void __launch_bounds__(256) split_kernel(
    const float* __restrict__ src, int ld,
    int M, int K, __nv_bfloat16* __restrict__ dst)
{
    int idx = blockIdx.x * 256 + threadIdx.x;
    if (idx >= M * K) return;
    int m = idx / K, k = idx - m * K;
    float f = src[(long long)m * ld + k];
    __nv_bfloat16 hi, lo;
    split3(f, hi, lo);
    __nv_bfloat16* r = dst + (long long)m * 2 * K;
    r[k] = hi; r[K + k] = lo;
}

// ======================= merged weight splits (ld==K contiguous) ==================
__global__ void __launch_bounds__(256) weight_split_kernel(
    const float* __restrict__ w_in, const float* __restrict__ w_xp,
    const float* __restrict__ w_dt, const float* __restrict__ w_qkv,
    const float* __restrict__ w_at, const float* __restrict__ w_out,
    __nv_bfloat16* __restrict__ winS, __nv_bfloat16* __restrict__ wxpS,
    __nv_bfloat16* __restrict__ wdtS, __nv_bfloat16* __restrict__ wqkvS,
    __nv_bfloat16* __restrict__ watS, __nv_bfloat16* __restrict__ woutS)
{
    int idx = blockIdx.x * 256 + threadIdx.x;
    const float* src; __nv_bfloat16* dst; int K;
    int rem = idx;
    if (rem < 589824)                 { src = w_in;  dst = winS;  K = 768; }
    else if ((rem -= 589824) < 20480) { src = w_xp;  dst = wxpS;  K = 256; }
    else if ((rem -= 20480) < 12288)  { src = w_dt;  dst = wdtS;  K = 48;  }
    else if ((rem -= 12288) < 196608) { src = w_qkv; dst = wqkvS; K = 256; }
    else if ((rem -= 196608) < 65536) { src = w_at;  dst = watS;  K = 256; }
    else                              { rem -= 65536; src = w_out; dst = woutS; K = 768; }
    int m = rem / K, k = rem - m * K;
    float f = src[(long long)m * K + k];
    __nv_bfloat16 hi, lo;
    split3(f, hi, lo);
    __nv_bfloat16* r = dst + (long long)m * 2 * K;
    r[k] = hi; r[K + k] = lo;
}

// ======================= HMMA bf16 NT GEMM, 128x64, split-2 3-pass =======================
// Kp = ORIGINAL K (elements per hi/lo half). lda/ldb = 2*Kp (hi at 0, lo at Kp).
// epi: 0 none, 1 +bias*bscale, 2 softplus(v + bias*bscale)
// osplit: C is bf16; write [hi, lo] at coff+c and coff+c+Kof (row stride ldc).
// dual: if splitx>0 and blockIdx.x>=splitx, switch to (A2,B2,C2,N2,ldc2), epi=0.
#define ASTR2 144
#define ASZ 18432      // 128*144
#define STG2 27648
__global__ void __launch_bounds__(256, 2) gemm_mma(
    const __nv_bfloat16* __restrict__ A, const __nv_bfloat16* __restrict__ B,
    float* __restrict__ C, int M, int Nglob, int Kp,
    int lda, int ldb, int ldc, int coff,
    const float* __restrict__ bias, float bscale, float alpha, int epi,
    int osplit, int Kof,
    const __nv_bfloat16* __restrict__ A2, const __nv_bfloat16* __restrict__ B2,
    float* __restrict__ C2, int N2, int ldc2, int splitx)
{
    extern __shared__ __align__(16) char smem[];
    uint32_t sb = smem_to_u32(smem);
    int tid = threadIdx.x;
    int bx = blockIdx.x;
    int n0;
    if (splitx && bx >= splitx) {
        A = A2; B = B2; C = C2; Nglob = N2; ldc = ldc2;
        epi = 0; osplit = 0; coff = 0;
        n0 = (bx - splitx) * 64;
    } else {
        n0 = bx * 64;
    }
    int m0 = blockIdx.y * 128;
    int NC = (Kp + 31) >> 5;

    // stage layout per row: 8 granules of 16B; t<4 = hi cols k0+t*8, t>=4 = lo
    auto load_stage = [&](int c) {
        int k0 = c * 32;
        uint32_t ab = sb + (c % 3) * STG2;
        uint32_t bb = ab + ASZ;
        #pragma unroll
        for (int i = 0; i < 4; i++) {            // A: 1024 granules
            int g = tid + i * 256;
            int r = g >> 3, t = g & 7;
            int kk = k0 + (t & 3) * 8;
            const __nv_bfloat16* src = A + (long long)(m0 + r) * lda + (t >= 4 ? Kp : 0) + kk;
            cp16(ab + r * ASTR2 + t * 16, src, kk < Kp);
        }
        #pragma unroll
        for (int i = 0; i < 2; i++) {            // B: 512 granules
            int g = tid + i * 256;
            int r = g >> 3, t = g & 7;
            int kk = k0 + (t & 3) * 8;
            const __nv_bfloat16* src = B + (long long)(n0 + r) * ldb + (t >= 4 ? Kp : 0) + kk;
            cp16(bb + r * ASTR2 + t * 16, src, (n0 + r) < Nglob && kk < Kp);
        }
        asm volatile("cp.async.commit_group;" ::: "memory");
    };

    int wid = tid >> 5, lane = tid & 31;
    int wm = wid & 3, wn = wid >> 2;            // 4x2 warps, warp tile 32x32
    int g = lane >> 2, tg = lane & 3;
    int l7 = lane & 7;

    // ldmatrix lane offsets (stage-relative; add ks*32; lo adds +64)
    uint32_t aoffH = (uint32_t)((wm * 32 + l7 + ((lane >> 3) & 1) * 8) * ASTR2 + (lane >> 4) * 16);
    uint32_t boffH = (uint32_t)((wn * 32 + (lane >> 4) * 8 + l7) * ASTR2 + ((lane >> 3) & 1) * 16);

    float acc[2][4][4] = {};

    load_stage(0);
    if (1 < NC) load_stage(1);

    for (int c = 0; c < NC; c++) {
        if (c + 1 < NC) { asm volatile("cp.async.wait_group 1;" ::: "memory"); }
        else            { asm volatile("cp.async.wait_group 0;" ::: "memory"); }
        __syncthreads();
        if (c + 2 < NC) load_stage(c + 2);

        uint32_t ab = sb + (c % 3) * STG2;
        uint32_t bb = ab + ASZ;
        #pragma unroll
        for (int ks = 0; ks < 2; ks++) {
            uint32_t ah0[4], ah1[4], al0[4], al1[4];
            uint32_t bh0[4], bh1[4], bl0[4], bl1[4];
            uint32_t ao = ab + aoffH + ks * 32;
            uint32_t bo = bb + boffH + ks * 32;
            ldsm4(ah0, ao);
            ldsm4(ah1, ao + 16 * ASTR2);
            ldsm4(al0, ao + 64);
            ldsm4(al1, ao + 64 + 16 * ASTR2);
            ldsm4(bh0, bo);
            ldsm4(bh1, bo + 16 * ASTR2);
            ldsm4(bl0, bo + 64);
            ldsm4(bl1, bo + 64 + 16 * ASTR2);
            // pass 1: Ah * Bh
            mma16816(acc[0][0], ah0, bh0 + 0);
            mma16816(acc[0][1], ah0, bh0 + 2);
            mma16816(acc[0][2], ah0, bh1 + 0);
            mma16816(acc[0][3], ah0, bh1 + 2);
            mma16816(acc[1][0], ah1, bh0 + 0);
            mma16816(acc[1][1], ah1, bh0 + 2);
            mma16816(acc[1][2], ah1, bh1 + 0);
            mma16816(acc[1][3], ah1, bh1 + 2);
            // pass 2: Ah * Bl
            mma16816(acc[0][0], ah0, bl0 + 0);
            mma16816(acc[0][1], ah0, bl0 + 2);
            mma16816(acc[0][2], ah0, bl1 + 0);
            mma16816(acc[0][3], ah0, bl1 + 2);
            mma16816(acc[1][0], ah1, bl0 + 0);
            mma16816(acc[1][1], ah1, bl0 + 2);
            mma16816(acc[1][2], ah1, bl1 + 0);
            mma16816(acc[1][3], ah1, bl1 + 2);
            // pass 3: Al * Bh
            mma16816(acc[0][0], al0, bh0 + 0);
            mma16816(acc[0][1], al0, bh0 + 2);
            mma16816(acc[0][2], al0, bh1 + 0);
            mma16816(acc[0][3], al0, bh1 + 2);
            mma16816(acc[1][0], al1, bh0 + 0);
            mma16816(acc[1][1], al1, bh0 + 2);
            mma16816(acc[1][2], al1, bh1 + 0);
            mma16816(acc[1][3], al1, bh1 + 2);
        }
    }
    __syncthreads();

    // ---- epilogue ----
    #pragma unroll
    for (int mi = 0; mi < 2; mi++) {
        int r0 = m0 + wm * 32 + mi * 16 + g;
        #pragma unroll
        for (int nj = 0; nj < 4; nj++) {
            int cc = n0 + wn * 32 + nj * 8 + tg * 2;
            if (cc >= Nglob) continue;
            #pragma unroll
            for (int hh = 0; hh < 2; hh++) {
                int rr = r0 + hh * 8;
                float v0 = acc[mi][nj][hh * 2 + 0] * alpha;
                float v1 = acc[mi][nj][hh * 2 + 1] * alpha;
                if (epi >= 1) { v0 += bias[cc] * bscale; v1 += bias[cc + 1] * bscale; }
                if (epi == 2) {
                    v0 = (v0 > 15.f) ? v0 : log1pf(__expf(v0));
                    v1 = (v1 > 15.f) ? v1 : log1pf(__expf(v1));
                }
                if (!osplit) {
                    *(float2*)&C[(long long)rr * ldc + coff + cc] = make_float2(v0, v1);
                } else {
                    __nv_bfloat16* Cb = (__nv_bfloat16*)C;
                    long long base = (long long)rr * ldc + coff + cc;
                    __nv_bfloat16 h0, l0, h1, l1;
                    split3(v0, h0, l0);
                    split3(v1, h1, l1);
                    Cb[base]       = h0;  Cb[base + 1]       = h1;
                    Cb[base + Kof] = l0;  Cb[base + Kof + 1] = l1;
                }
            }
        }
    }
}

// ======================= fused flash attention (writes [hi|lo] oS) =======================
#define SQ 208
#define SV 272
#define OFF_VTH 26624
#define OFF_VTL 35328
#define OFF_RMAX 44032
#define OFF_RSUM 45056
__global__ void __launch_bounds__(256, 1) flash_kernel(
    const float* __restrict__ qkv, __nv_bfloat16* __restrict__ oS)
{
    __shared__ __align__(16) char smem[46080];
    uint32_t sb = smem_to_u32(smem);
    float* rmax = (float*)(smem + OFF_RMAX);
    float* rsum = (float*)(smem + OFF_RSUM);
    int tid = threadIdx.x;
    int wid = tid >> 5, lane = tid & 31;
    int wm = wid & 3, wn = wid >> 2;
    int g = lane >> 2, tg = lane & 3;
    int z = blockIdx.y;
    int b = z >> 3, h = z & 7;
    int q0 = blockIdx.x * 128;
    const float alpha = 0.17677669529663687f;
    const float* qkvb = qkv + (long long)b * 1024 * 768 + h * 32;

    #pragma unroll
    for (int j = 0; j < 16; j++) {
        int i = tid + j * 256;
        int row = i >> 5, d = i & 31;
        float f = qkvb[(long long)(q0 + row) * 768 + d] * alpha;
        __nv_bfloat16 hi, lo;
        split3(f, hi, lo);
        *(__nv_bfloat16*)(smem + row * SQ + d * 2) = hi;
        *(__nv_bfloat16*)(smem + row * SQ + 64 + d * 2) = hi;
        *(__nv_bfloat16*)(smem + row * SQ + 128 + d * 2) = lo;
    }
    __syncthreads();
    uint32_t qa[6][2][4];
    #pragma unroll
    for (int kb = 0; kb < 6; kb++)
        #pragma unroll
        for (int mi = 0; mi < 2; mi++) {
            uint32_t base = sb + (wm * 32 + mi * 16 + g) * SQ + kb * 32 + tg * 4;
            qa[kb][mi][0] = lds32(base);
            qa[kb][mi][1] = lds32(base + 8 * SQ);
            qa[kb][mi][2] = lds32(base + 16);
            qa[kb][mi][3] = lds32(base + 8 * SQ + 16);
        }

    float accO[2][4][4] = {};
    float m_run[2][2] = {{-1e30f, -1e30f}, {-1e30f, -1e30f}};
    float l_run[2][2] = {{0.f, 0.f}, {0.f, 0.f}};

    for (int t = 0; t < 8; t++) {
        int j0 = t * 128;
        __syncthreads();
        #pragma unroll
        for (int j = 0; j < 16; j++) {
            int i = tid + j * 256;
            int key = i >> 5, d = i & 31;
            const float* src = qkvb + (long long)(j0 + key) * 768;
            float kf = src[256 + d];
            __nv_bfloat16 khi, klo;
            split3(kf, khi, klo);
            *(__nv_bfloat16*)(smem + key * SQ + d * 2) = khi;
            *(__nv_bfloat16*)(smem + key * SQ + 64 + d * 2) = klo;
            *(__nv_bfloat16*)(smem + key * SQ + 128 + d * 2) = khi;
            float vf = src[512 + d];
            __nv_bfloat16 vhi, vlo;
            split3(vf, vhi, vlo);
            *(__nv_bfloat16*)(smem + OFF_VTH + d * SV + key * 2) = vhi;
            *(__nv_bfloat16*)(smem + OFF_VTL + d * SV + key * 2) = vlo;
        }
        __syncthreads();

        float accS[2][8][4] = {};
        #pragma unroll
        for (int kb = 0; kb < 6; kb++) {
            uint32_t bfr[8][2];
            #pragma unroll
            for (int nj = 0; nj < 8; nj++) {
                uint32_t base = sb + (wn * 64 + nj * 8 + g) * SQ + kb * 32 + tg * 4;
                bfr[nj][0] = lds32(base);
                bfr[nj][1] = lds32(base + 16);
            }
            #pragma unroll
            for (int mi = 0; mi < 2; mi++)
                #pragma unroll
                for (int nj = 0; nj < 8; nj++)
                    mma16816(accS[mi][nj], qa[kb][mi], bfr[nj]);
        }

        float mx[2][2];
        #pragma unroll
        for (int mi = 0; mi < 2; mi++)
            #pragma unroll
            for (int hh = 0; hh < 2; hh++) {
                float m = -1e30f;
                #pragma unroll
                for (int nj = 0; nj < 8; nj++)
                    m = fmaxf(m, fmaxf(accS[mi][nj][hh * 2], accS[mi][nj][hh * 2 + 1]));
                m = fmaxf(m, __shfl_xor_sync(0xffffffffu, m, 1));
                m = fmaxf(m, __shfl_xor_sync(0xffffffffu, m, 2));
                mx[mi][hh] = m;
            }
        if (tg == 0) {
            #pragma unroll
            for (int mi = 0; mi < 2; mi++)
                #pragma unroll
                for (int hh = 0; hh < 2; hh++)
                    rmax[wn * 128 + wm * 32 + mi * 16 + hh * 8 + g] = mx[mi][hh];
        }
        __syncthreads();

        float fsc[2][2], mnew[2][2], ls[2][2];
        #pragma unroll
        for (int mi = 0; mi < 2; mi++)
            #pragma unroll
            for (int hh = 0; hh < 2; hh++) {
                int r = wm * 32 + mi * 16 + hh * 8 + g;
                float tm = fmaxf(rmax[r], rmax[128 + r]);
                float mn = fmaxf(m_run[mi][hh], tm);
                mnew[mi][hh] = mn;
                fsc[mi][hh] = __expf(m_run[mi][hh] - mn);
                ls[mi][hh] = 0.f;
            }
        #pragma unroll
        for (int mi = 0; mi < 2; mi++)
            #pragma unroll
            for (int hh = 0; hh < 2; hh++) {
                float mn = mnew[mi][hh];
                float s = 0.f;
                #pragma unroll
                for (int nj = 0; nj < 8; nj++) {
                    float p0 = __expf(accS[mi][nj][hh * 2] - mn);
                    float p1 = __expf(accS[mi][nj][hh * 2 + 1] - mn);
                    accS[mi][nj][hh * 2] = p0;
                    accS[mi][nj][hh * 2 + 1] = p1;
                    s += p0 + p1;
                }
                ls[mi][hh] = s;
                float f = fsc[mi][hh];
                #pragma unroll
                for (int nj2 = 0; nj2 < 4; nj2++) {
                    accO[mi][nj2][hh * 2] *= f;
                    accO[mi][nj2][hh * 2 + 1] *= f;
                }
            }
        #pragma unroll
        for (int mi = 0; mi < 2; mi++)
            #pragma unroll
            for (int hh = 0; hh < 2; hh++) {
                float s = ls[mi][hh];
                s += __shfl_xor_sync(0xffffffffu, s, 1);
                s += __shfl_xor_sync(0xffffffffu, s, 2);
                ls[mi][hh] = s;
            }
        if (tg == 0) {
            #pragma unroll
            for (int mi = 0; mi < 2; mi++)
                #pragma unroll
                for (int hh = 0; hh < 2; hh++)
                    rsum[wn * 128 + wm * 32 + mi * 16 + hh * 8 + g] = ls[mi][hh];
        }
        __syncthreads();
        #pragma unroll
        for (int mi = 0; mi < 2; mi++)
            #pragma unroll
            for (int hh = 0; hh < 2; hh++) {
                int r = wm * 32 + mi * 16 + hh * 8 + g;
                l_run[mi][hh] = l_run[mi][hh] * fsc[mi][hh] + rsum[r] + rsum[128 + r];
                m_run[mi][hh] = mnew[mi][hh];
            }

        #pragma unroll
        for (int kb = 0; kb < 4; kb++) {
            uint32_t pah[2][4], pal[2][4];
            #pragma unroll
            for (int mi = 0; mi < 2; mi++) {
                float x0 = accS[mi][2 * kb][0], x1 = accS[mi][2 * kb][1];
                float x2 = accS[mi][2 * kb][2], x3 = accS[mi][2 * kb][3];
                float y0 = accS[mi][2 * kb + 1][0], y1 = accS[mi][2 * kb + 1][1];
                float y2 = accS[mi][2 * kb + 1][2], y3 = accS[mi][2 * kb + 1][3];
                pah[mi][0] = packh(x0, x1);
                pah[mi][1] = packh(x2, x3);
                pah[mi][2] = packh(y0, y1);
                pah[mi][3] = packh(y2, y3);
                __nv_bfloat162 t0 = *(__nv_bfloat162*)&pah[mi][0];
                __nv_bfloat162 t1 = *(__nv_bfloat162*)&pah[mi][1];
                __nv_bfloat162 t2 = *(__nv_bfloat162*)&pah[mi][2];
                __nv_bfloat162 t3 = *(__nv_bfloat162*)&pah[mi][3];
                pal[mi][0] = packh(x0 - __bfloat162float(t0.x), x1 - __bfloat162float(t0.y));
                pal[mi][1] = packh(x2 - __bfloat162float(t1.x), x3 - __bfloat162float(t1.y));
                pal[mi][2] = packh(y0 - __bfloat162float(t2.x), y1 - __bfloat162float(t2.y));
                pal[mi][3] = packh(y2 - __bfloat162float(t3.x), y3 - __bfloat162float(t3.y));
            }
            uint32_t vbh[4][2], vbl[4][2];
            int kcol = (wn * 64 + kb * 16 + tg * 2) * 2;
            #pragma unroll
            for (int nj2 = 0; nj2 < 4; nj2++) {
                uint32_t bh = sb + OFF_VTH + (nj2 * 8 + g) * SV + kcol;
                uint32_t bl = sb + OFF_VTL + (nj2 * 8 + g) * SV + kcol;
                vbh[nj2][0] = lds32(bh);  vbh[nj2][1] = lds32(bh + 16);
                vbl[nj2][0] = lds32(bl);  vbl[nj2][1] = lds32(bl + 16);
            }
            #pragma unroll
            for (int mi = 0; mi < 2; mi++)
                #pragma unroll
                for (int nj2 = 0; nj2 < 4; nj2++) {
                    mma16816(accO[mi][nj2], pah[mi], vbh[nj2]);
                    mma16816(accO[mi][nj2], pah[mi], vbl[nj2]);
                    mma16816(accO[mi][nj2], pal[mi], vbh[nj2]);
                }
        }
    }

    // ---- cross-warp O reduction + normalize + [hi|lo] store to oS ----
    __syncthreads();
    float* Ob = (float*)smem;
    if (wn == 0) {
        #pragma unroll
        for (int mi = 0; mi < 2; mi++)
            #pragma unroll
            for (int hh = 0; hh < 2; hh++) {
                int r = wm * 32 + mi * 16 + hh * 8 + g;
                #pragma unroll
                for (int nj2 = 0; nj2 < 4; nj2++) {
                    Ob[r * 36 + nj2 * 8 + tg * 2]     = accO[mi][nj2][hh * 2];
                    Ob[r * 36 + nj2 * 8 + tg * 2 + 1] = accO[mi][nj2][hh * 2 + 1];
                }
            }
    }
    __syncthreads();
    if (wn == 1) {
        #pragma unroll
        for (int mi = 0; mi < 2; mi++)
            #pragma unroll
            for (int hh = 0; hh < 2; hh++) {
                int r = wm * 32 + mi * 16 + hh * 8 + g;
                float inv = 1.f / l_run[mi][hh];
                #pragma unroll
                for (int nj2 = 0; nj2 < 4; nj2++) {
                    int d = nj2 * 8 + tg * 2;
                    float v0 = (Ob[r * 36 + d]     + accO[mi][nj2][hh * 2])     * inv;
                    float v1 = (Ob[r * 36 + d + 1] + accO[mi][nj2][hh * 2 + 1]) * inv;
                    __nv_bfloat16 h0, l0, h1, l1;
                    split3(v0, h0, l0);
                    split3(v1, h1, l1);
                    long long base = (long long)(b * 1024 + q0 + r) * 512 + h * 32 + d;
                    oS[base]       = h0;  oS[base + 1]       = h1;
                    oS[base + 256] = l0;  oS[base + 256 + 1] = l1;
                }
            }
    }
}

// ======================= depthwise conv + SiLU, fused [hi|lo] outputs =======================
__global__ void __launch_bounds__(256) conv_silu_kernel(
    const float* __restrict__ xzy,
    const float* __restrict__ wx, const float* __restrict__ wz, const float* __restrict__ wy,
    float* __restrict__ xc, __nv_bfloat16* __restrict__ xcS,
    __nv_bfloat16* __restrict__ catS, __nv_bfloat16* __restrict__ ycS)
{
    int idx = blockIdx.x * 256 + threadIdx.x;
    int d = idx & 255;
    int m = idx >> 8;
    int l = m & 1023;
    const float* base = xzy + (long long)m * 768;
    float a0 = 0.f, a1 = 0.f, a2 = 0.f;
    #pragma unroll
    for (int k = 0; k < 4; k++) {
        int li = l + k - 1;
        if (li < 0 || li >= 1024) continue;
        const float* row = base + (long long)(k - 1) * 768;
        a0 = fmaf(row[d],       wx[d * 4 + k], a0);
        a1 = fmaf(row[256 + d], wz[d * 4 + k], a1);
        a2 = fmaf(row[512 + d], wy[d * 4 + k], a2);
    }
    a0 = a0 / (1.f + __expf(-a0));
    a1 = a1 / (1.f + __expf(-a1));
    a2 = a2 / (1.f + __expf(-a2));
    xc[idx] = a0;
    __nv_bfloat16 hi, lo;
    split3(a0, hi, lo);                         // xcS [hi|lo], stride 512
    xcS[(long long)m * 512 + d] = hi;
    xcS[(long long)m * 512 + 256 + d] = lo;
    split3(a1, hi, lo);                         // z -> catS cols [256,512), stride 1536
    catS[(long long)m * 1536 + 256 + d] = hi;
    catS[(long long)m * 1536 + 768 + 256 + d] = lo;
    split3(a2, hi, lo);                         // ycS [hi|lo]
    ycS[(long long)m * 512 + d] = hi;
    ycS[(long long)m * 512 + 256 + d] = lo;
}

// ======================= selective scan (writes [hi|lo] into catS cols [0,256)) ==============
__global__ void __launch_bounds__(256) scan_kernel(
    const float* __restrict__ delta, const float* __restrict__ xc,
    const float* __restrict__ xdbl, const float* __restrict__ A_log,
    const float* __restrict__ D_param, __nv_bfloat16* __restrict__ catS)
{
    int t = blockIdx.x * 256 + threadIdx.x;
    int lane = t & 15;
    int p = t >> 4;
    int b = p >> 8;
    int d = p & 255;
    float Acoef = -__expf(A_log[d * 16 + lane]);
    float Dd = D_param[d];
    float h = 0.f;
    const float* dptr = delta + (long long)b * 1024 * 256 + d;
    const float* xptr = xc    + (long long)b * 1024 * 256 + d;
    const float* bptr = xdbl  + (long long)b * 1024 * 80 + 48 + lane;
    const float* cptr = bptr + 16;
    __nv_bfloat16* optr = catS + (long long)b * 1024 * 1536 + d;
    #pragma unroll 4
    for (int l = 0; l < 1024; l++) {
        float dl = dptr[(long long)l * 256];
        float xv = xptr[(long long)l * 256];
        float Bv = bptr[(long long)l * 80];
        float Cv = cptr[(long long)l * 80];
        float dA = __expf(dl * Acoef);
        h = fmaf(dA, h, dl * xv * Bv);
        float yv = h * Cv;
        yv += __shfl_xor_sync(0xffffffffu, yv, 1);
        yv += __shfl_xor_sync(0xffffffffu, yv, 2);
        yv += __shfl_xor_sync(0xffffffffu, yv, 4);
        yv += __shfl_xor_sync(0xffffffffu, yv, 8);
        if (lane == 0) {
            float v = fmaf(xv, Dd, yv);
            __nv_bfloat16 hi, lo;
            split3(v, hi, lo);
            optr[(long long)l * 1536] = hi;
            optr[(long long)l * 1536 + 768] = lo;
        }
    }
}

// ======================= host launcher =======================
extern "C" void kernel_launch(void* const* d_in, const int* in_sizes, int n_in,
                              void* d_out, int out_size)
{
    const float* hs          = (const float*)d_in[0];
    const float* in_proj_w   = (const float*)d_in[1];
    const float* conv_wx     = (const float*)d_in[2];
    const float* conv_wz     = (const float*)d_in[3];
    const float* conv_wy     = (const float*)d_in[4];
    const float* x_proj_w    = (const float*)d_in[5];
    const float* dt_proj_w   = (const float*)d_in[6];
    const float* dt_proj_b   = (const float*)d_in[7];
    const float* A_log       = (const float*)d_in[8];
    const float* D_param     = (const float*)d_in[9];
    const float* out_proj_w  = (const float*)d_in[10];
    const float* qkv_w       = (const float*)d_in[11];
    const float* attn_proj_w = (const float*)d_in[12];
    const float* attn_proj_b = (const float*)d_in[13];
    float* out = (float*)d_out;

    cudaFuncSetAttribute(gemm_mma, cudaFuncAttributeMaxDynamicSharedMemorySize, 3 * STG2);

    float *xzy, *xc, *xdbl, *delta, *qkv;
    cudaGetSymbolAddress((void**)&xzy,   g_xzy);
    cudaGetSymbolAddress((void**)&xc,    g_xc);
    cudaGetSymbolAddress((void**)&xdbl,  g_xdbl);
    cudaGetSymbolAddress((void**)&delta, g_delta);
    cudaGetSymbolAddress((void**)&qkv,   g_qkv);

    __nv_bfloat16 *hsS, *winS, *xcS, *wxpS, *dtS, *wdtS, *ycS, *wqkvS;
    __nv_bfloat16 *oS, *watS, *catS, *woutS;
    cudaGetSymbolAddress((void**)&hsS,   g_hsS);
    cudaGetSymbolAddress((void**)&winS,  g_winS);
    cudaGetSymbolAddress((void**)&xcS,   g_xcS);
    cudaGetSymbolAddress((void**)&wxpS,  g_wxpS);
    cudaGetSymbolAddress((void**)&dtS,   g_dtS);
    cudaGetSymbolAddress((void**)&wdtS,  g_wdtS);
    cudaGetSymbolAddress((void**)&ycS,   g_ycS);
    cudaGetSymbolAddress((void**)&wqkvS, g_wqkvS);
    cudaGetSymbolAddress((void**)&oS,    g_oS);
    cudaGetSymbolAddress((void**)&watS,  g_watS);
    cudaGetSymbolAddress((void**)&catS,  g_catS);
    cudaGetSymbolAddress((void**)&woutS, g_woutS);

    const int DS = 3 * STG2;

    // 1) input + all-weight splits ([hi|lo] layout)
    split_kernel<<<12288, 256>>>(hs, 768, 4096, 768, hsS);
    weight_split_kernel<<<5760, 256>>>(in_proj_w, x_proj_w, dt_proj_w, qkv_w,
        attn_proj_w, out_proj_w, winS, wxpS, wdtS, wqkvS, watS, woutS);

    // 2) in_proj: xzy = hs @ in_proj_w^T   (K=768)
    gemm_mma<<<dim3(12, 32), 256, DS>>>(hsS, winS, xzy, 4096, 768, 768,
        1536, 1536, 768, 0, nullptr, 0.f, 1.f, 0, 0, 0,
        nullptr, nullptr, nullptr, 0, 0, 0);

    // 3) depthwise conv + SiLU (fused split outputs)
    conv_silu_kernel<<<4096, 256>>>(xzy, conv_wx, conv_wz, conv_wy, xc, xcS, catS, ycS);

    // 4) DUAL: qkv = yc @ qkv_w^T (bx<12)  ‖  x_dbl = xc @ x_proj_w^T (bx>=12)   (K=256)
    gemm_mma<<<dim3(14, 32), 256, DS>>>(ycS, wqkvS, qkv, 4096, 768, 256,
        512, 512, 768, 0, nullptr, 0.f, 1.f, 0, 0, 0,
        xcS, wxpS, xdbl, 80, 80, 12);

    // 5) fused flash attention -> oS ([hi|lo])
    flash_kernel<<<dim3(8, 32), 256>>>(qkv, oS);

    // 6) dt split + delta = softplus(dt @ dt_proj_w^T + 2*b)   (K=48)
    split_kernel<<<768, 256>>>(xdbl, 80, 4096, 48, dtS);
    gemm_mma<<<dim3(4, 32), 256, DS>>>(dtS, wdtS, delta, 4096, 256, 48,
        96, 96, 256, 0, dt_proj_b, 2.f, 1.f, 2, 0, 0,
        nullptr, nullptr, nullptr, 0, 0, 0);

    // 7) selective scan -> catS cols [0,256) ([hi|lo])
    scan_kernel<<<64, 256>>>(delta, xc, xdbl, A_log, D_param, catS);

    // 8) y_att = o @ attn_proj_w^T + b -> catS cols [512,768) ([hi|lo] epilogue)
    gemm_mma<<<dim3(4, 32), 256, DS>>>(oS, watS, (float*)catS, 4096, 256, 256,
        512, 512, 1536, 512, attn_proj_b, 1.f, 1.f, 1, 1, 768,
        nullptr, nullptr, nullptr, 0, 0, 0);

    // 9) out = catS @ out_proj_w^T   (K=768)
    gemm_mma<<<dim3(12, 32), 256, DS>>>(catS, woutS, out, 4096, 768, 768,
        1536, 1536, 768, 0, nullptr, 0.f, 1.f, 0, 0, 0,
        nullptr, nullptr, nullptr, 0, 0, 0);
}

// round 10
// speedup vs baseline: 1.6589x; 1.3239x over previous
#include <cuda_runtime.h>
#include <cuda_bf16.h>
#include <cuda_fp16.h>
#include <math.h>
#include <stdint.h>

// Problem constants: B=4, L=1024, DM=768, DC=256, N=16, R=48, K=4, H=8, HD=32
// GEMMs: single-pass fp16 operands (K-wide), fp32 accumulate.
// Flash attention: internal split-bf16 (unchanged), fp16 output.

// ======================= scratch buffers (static; no allocation) =======================
__device__ float g_xzy[4096 * 768];
__device__ float g_xc[4096 * 256];
__device__ float g_xdbl[4096 * 80];
__device__ float g_delta[4096 * 256];
__device__ float g_qkv[4096 * 768];

__device__ __half g_hsS[4096 * 768];
__device__ __half g_winS[768 * 768];
__device__ __half g_xcS[4096 * 256];
__device__ __half g_wxpS[80 * 256];
__device__ __half g_dtS[4096 * 48];
__device__ __half g_wdtS[256 * 48];
__device__ __half g_ycS[4096 * 256];
__device__ __half g_wqkvS[768 * 256];
__device__ __half g_oS[4096 * 256];
__device__ __half g_watS[256 * 256];
__device__ __half g_catS[4096 * 768];
__device__ __half g_woutS[768 * 768];

// ======================= small asm helpers =======================
__device__ __forceinline__ uint32_t smem_to_u32(const void* smem_ptr) {
    uint32_t addr;
    asm("{ .reg .u64 tmp; cvta.to.shared.u64 tmp, %1; cvt.u32.u64 %0, tmp; }"
        : "=r"(addr) : "l"(smem_ptr));
    return addr;
}

__device__ __forceinline__ uint32_t lds32(uint32_t a) {
    uint32_t v;
    asm volatile("ld.shared.b32 %0, [%1];" : "=r"(v) : "r"(a));
    return v;
}

__device__ __forceinline__ void ldsm4(uint32_t* r, uint32_t a) {
    asm volatile("ldmatrix.sync.aligned.m8n8.x4.shared.b16 {%0,%1,%2,%3}, [%4];"
                 : "=r"(r[0]), "=r"(r[1]), "=r"(r[2]), "=r"(r[3]) : "r"(a));
}

__device__ __forceinline__ void cp16(uint32_t dst, const void* src, bool pred) {
    int sz = pred ? 16 : 0;
    asm volatile("cp.async.cg.shared.global [%0], [%1], 16, %2;"
                 :: "r"(dst), "l"(src), "r"(sz) : "memory");
}

// bf16 MMA (flash attention)
__device__ __forceinline__ void mma_bf16(float* c, const uint32_t* a, const uint32_t* b) {
    asm volatile(
        "mma.sync.aligned.m16n8k16.row.col.f32.bf16.bf16.f32 "
        "{%0,%1,%2,%3}, {%4,%5,%6,%7}, {%8,%9}, {%0,%1,%2,%3};"
        : "+f"(c[0]), "+f"(c[1]), "+f"(c[2]), "+f"(c[3])
        : "r"(a[0]), "r"(a[1]), "r"(a[2]), "r"(a[3]), "r"(b[0]), "r"(b[1]));
}

// fp16 MMA (projection GEMMs)
__device__ __forceinline__ void mma_f16(float* c, const uint32_t* a, const uint32_t* b) {
    asm volatile(
        "mma.sync.aligned.m16n8k16.row.col.f32.f16.f16.f32 "
        "{%0,%1,%2,%3}, {%4,%5,%6,%7}, {%8,%9}, {%0,%1,%2,%3};"
        : "+f"(c[0]), "+f"(c[1]), "+f"(c[2]), "+f"(c[3])
        : "r"(a[0]), "r"(a[1]), "r"(a[2]), "r"(a[3]), "r"(b[0]), "r"(b[1]));
}

__device__ __forceinline__ uint32_t packh(float x, float y) {
    __nv_bfloat162 t = __floats2bfloat162_rn(x, y);
    return *(uint32_t*)&t;
}

__device__ __forceinline__ void split3(float f, __nv_bfloat16& hi, __nv_bfloat16& lo) {
    hi = __float2bfloat16(f);
    lo = __float2bfloat16(f - __bfloat162float(hi));
}

// ======================= fp32 -> fp16 conversion =======================
__global__ void __launch_bounds__(256) half_kernel(
    const float* __restrict__ src, int ld,
    int M, int K, __half* __restrict__ dst)
{
    int idx = blockIdx.x * 256 + threadIdx.x;
    if (idx >= M * K) return;
    int m = idx / K, k = idx - m * K;
    dst[(long long)m * K + k] = __float2half_rn(src[(long long)m * ld + k]);
}

// ======================= merged weight conversions (ld==K contiguous) ==================
__global__ void __launch_bounds__(256) weight_half_kernel(
    const float* __restrict__ w_in, const float* __restrict__ w_xp,
    const float* __restrict__ w_dt, const float* __restrict__ w_qkv,
    const float* __restrict__ w_at, const float* __restrict__ w_out,
    __half* __restrict__ winS, __half* __restrict__ wxpS,
    __half* __restrict__ wdtS, __half* __restrict__ wqkvS,
    __half* __restrict__ watS, __half* __restrict__ woutS)
{
    int idx = blockIdx.x * 256 + threadIdx.x;
    const float* src; __half* dst;
    int rem = idx;
    if (rem < 589824)                 { src = w_in;  dst = winS;  }
    else if ((rem -= 589824) < 20480) { src = w_xp;  dst = wxpS;  }
    else if ((rem -= 20480) < 12288)  { src = w_dt;  dst = wdtS;  }
    else if ((rem -= 12288) < 196608) { src = w_qkv; dst = wqkvS; }
    else if ((rem -= 196608) < 65536) { src = w_at;  dst = watS;  }
    else                              { rem -= 65536; src = w_out; dst = woutS; }
    dst[rem] = __float2half_rn(src[rem]);
}

// ======================= HMMA fp16 NT GEMM, 128x64x32, 3-stage + ldmatrix ====================
// epi: 0 none, 1 +bias*bscale, 2 softplus(v + bias*bscale)
// ohalf: if 1, C is a __half buffer; write fp16 at coff+c (row stride ldc elements).
// dual: if splitx>0 and blockIdx.x>=splitx, switch to (A2,B2,C2,N2,ldc2), epi=0.
#define ASTR 80
#define STG 15360      // 128*80 (A) + 64*80 (B)
__global__ void __launch_bounds__(256, 3) gemm_mma(
    const __half* __restrict__ A, const __half* __restrict__ B,
    float* __restrict__ C, int M, int Nglob, int Kp,
    int lda, int ldb, int ldc, int coff,
    const float* __restrict__ bias, float bscale, float alpha, int epi,
    int ohalf,
    const __half* __restrict__ A2, const __half* __restrict__ B2,
    float* __restrict__ C2, int N2, int ldc2, int splitx)
{
    __shared__ __align__(16) char smem[3 * STG];
    uint32_t sb = smem_to_u32(smem);
    int tid = threadIdx.x;
    int bx = blockIdx.x;
    int n0;
    if (splitx && bx >= splitx) {
        A = A2; B = B2; C = C2; Nglob = N2; ldc = ldc2;
        epi = 0; ohalf = 0; coff = 0;
        n0 = (bx - splitx) * 64;
    } else {
        n0 = bx * 64;
    }
    int m0 = blockIdx.y * 128;
    int NC = (Kp + 31) >> 5;

    auto load_stage = [&](int c) {
        int k0 = c * 32;
        uint32_t ab = sb + (c % 3) * STG;
        uint32_t bb = ab + 10240;
        #pragma unroll
        for (int i = 0; i < 2; i++) {
            int gg = tid + i * 256;
            int r = gg >> 2, c16 = gg & 3;
            int k = k0 + c16 * 8;
            cp16(ab + r * ASTR + c16 * 16, A + (long long)(m0 + r) * lda + k, k < Kp);
        }
        {
            int r = tid >> 2, c16 = tid & 3;
            int k = k0 + c16 * 8;
            cp16(bb + r * ASTR + c16 * 16, B + (long long)(n0 + r) * ldb + k,
                 (n0 + r) < Nglob && k < Kp);
        }
        asm volatile("cp.async.commit_group;" ::: "memory");
    };

    int wid = tid >> 5, lane = tid & 31;
    int wm = wid & 3, wn = wid >> 2;          // 4x2 warps, warp tile 32x32
    int g = lane >> 2, tg = lane & 3;
    int l7 = lane & 7;

    uint32_t aoff0 = (uint32_t)((wm * 32 + l7 + ((lane >> 3) & 1) * 8) * ASTR + (lane >> 4) * 16);
    uint32_t aoff1 = aoff0 + 16 * ASTR;
    uint32_t boff0 = (uint32_t)((wn * 32 + (lane >> 4) * 8 + l7) * ASTR + ((lane >> 3) & 1) * 16);
    uint32_t boff1 = boff0 + 16 * ASTR;

    float acc[2][4][4] = {};

    load_stage(0);
    if (1 < NC) load_stage(1);

    for (int c = 0; c < NC; c++) {
        if (c + 1 < NC) { asm volatile("cp.async.wait_group 1;" ::: "memory"); }
        else            { asm volatile("cp.async.wait_group 0;" ::: "memory"); }
        __syncthreads();
        if (c + 2 < NC) load_stage(c + 2);

        uint32_t ab = sb + (c % 3) * STG;
        uint32_t bb = ab + 10240;
        #pragma unroll
        for (int ks = 0; ks < 2; ks++) {
            uint32_t a0[4], a1[4], b0[4], b1[4];
            ldsm4(a0, ab + aoff0 + ks * 32);
            ldsm4(a1, ab + aoff1 + ks * 32);
            ldsm4(b0, bb + boff0 + ks * 32);
            ldsm4(b1, bb + boff1 + ks * 32);
            mma_f16(acc[0][0], a0, b0 + 0);
            mma_f16(acc[0][1], a0, b0 + 2);
            mma_f16(acc[0][2], a0, b1 + 0);
            mma_f16(acc[0][3], a0, b1 + 2);
            mma_f16(acc[1][0], a1, b0 + 0);
            mma_f16(acc[1][1], a1, b0 + 2);
            mma_f16(acc[1][2], a1, b1 + 0);
            mma_f16(acc[1][3], a1, b1 + 2);
        }
    }
    __syncthreads();

    // ---- epilogue ----
    #pragma unroll
    for (int mi = 0; mi < 2; mi++) {
        int r0 = m0 + wm * 32 + mi * 16 + g;
        #pragma unroll
        for (int nj = 0; nj < 4; nj++) {
            int cc = n0 + wn * 32 + nj * 8 + tg * 2;
            if (cc >= Nglob) continue;
            #pragma unroll
            for (int hh = 0; hh < 2; hh++) {
                int rr = r0 + hh * 8;
                float v0 = acc[mi][nj][hh * 2 + 0] * alpha;
                float v1 = acc[mi][nj][hh * 2 + 1] * alpha;
                if (epi >= 1) { v0 += bias[cc] * bscale; v1 += bias[cc + 1] * bscale; }
                if (epi == 2) {
                    v0 = (v0 > 15.f) ? v0 : log1pf(__expf(v0));
                    v1 = (v1 > 15.f) ? v1 : log1pf(__expf(v1));
                }
                if (!ohalf) {
                    *(float2*)&C[(long long)rr * ldc + coff + cc] = make_float2(v0, v1);
                } else {
                    __half* Cb = (__half*)C;
                    long long base = (long long)rr * ldc + coff + cc;
                    __half2 hv = __floats2half2_rn(v0, v1);
                    *(__half2*)&Cb[base] = hv;
                }
            }
        }
    }
}

// ======================= fused flash attention (split-bf16 inside, fp16 out) ================
#define SQ 208
#define SV 272
#define OFF_VTH 26624
#define OFF_VTL 35328
#define OFF_RMAX 44032
#define OFF_RSUM 45056
__global__ void __launch_bounds__(256, 1) flash_kernel(
    const float* __restrict__ qkv, __half* __restrict__ oS)
{
    __shared__ __align__(16) char smem[46080];
    uint32_t sb = smem_to_u32(smem);
    float* rmax = (float*)(smem + OFF_RMAX);
    float* rsum = (float*)(smem + OFF_RSUM);
    int tid = threadIdx.x;
    int wid = tid >> 5, lane = tid & 31;
    int wm = wid & 3, wn = wid >> 2;
    int g = lane >> 2, tg = lane & 3;
    int z = blockIdx.y;
    int b = z >> 3, h = z & 7;
    int q0 = blockIdx.x * 128;
    const float alpha = 0.17677669529663687f;
    const float* qkvb = qkv + (long long)b * 1024 * 768 + h * 32;

    #pragma unroll
    for (int j = 0; j < 16; j++) {
        int i = tid + j * 256;
        int row = i >> 5, d = i & 31;
        float f = qkvb[(long long)(q0 + row) * 768 + d] * alpha;
        __nv_bfloat16 hi, lo;
        split3(f, hi, lo);
        *(__nv_bfloat16*)(smem + row * SQ + d * 2) = hi;
        *(__nv_bfloat16*)(smem + row * SQ + 64 + d * 2) = hi;
        *(__nv_bfloat16*)(smem + row * SQ + 128 + d * 2) = lo;
    }
    __syncthreads();
    uint32_t qa[6][2][4];
    #pragma unroll
    for (int kb = 0; kb < 6; kb++)
        #pragma unroll
        for (int mi = 0; mi < 2; mi++) {
            uint32_t base = sb + (wm * 32 + mi * 16 + g) * SQ + kb * 32 + tg * 4;
            qa[kb][mi][0] = lds32(base);
            qa[kb][mi][1] = lds32(base + 8 * SQ);
            qa[kb][mi][2] = lds32(base + 16);
            qa[kb][mi][3] = lds32(base + 8 * SQ + 16);
        }

    float accO[2][4][4] = {};
    float m_run[2][2] = {{-1e30f, -1e30f}, {-1e30f, -1e30f}};
    float l_run[2][2] = {{0.f, 0.f}, {0.f, 0.f}};

    for (int t = 0; t < 8; t++) {
        int j0 = t * 128;
        __syncthreads();
        #pragma unroll
        for (int j = 0; j < 16; j++) {
            int i = tid + j * 256;
            int key = i >> 5, d = i & 31;
            const float* src = qkvb + (long long)(j0 + key) * 768;
            float kf = src[256 + d];
            __nv_bfloat16 khi, klo;
            split3(kf, khi, klo);
            *(__nv_bfloat16*)(smem + key * SQ + d * 2) = khi;
            *(__nv_bfloat16*)(smem + key * SQ + 64 + d * 2) = klo;
            *(__nv_bfloat16*)(smem + key * SQ + 128 + d * 2) = khi;
            float vf = src[512 + d];
            __nv_bfloat16 vhi, vlo;
            split3(vf, vhi, vlo);
            *(__nv_bfloat16*)(smem + OFF_VTH + d * SV + key * 2) = vhi;
            *(__nv_bfloat16*)(smem + OFF_VTL + d * SV + key * 2) = vlo;
        }
        __syncthreads();

        float accS[2][8][4] = {};
        #pragma unroll
        for (int kb = 0; kb < 6; kb++) {
            uint32_t bfr[8][2];
            #pragma unroll
            for (int nj = 0; nj < 8; nj++) {
                uint32_t base = sb + (wn * 64 + nj * 8 + g) * SQ + kb * 32 + tg * 4;
                bfr[nj][0] = lds32(base);
                bfr[nj][1] = lds32(base + 16);
            }
            #pragma unroll
            for (int mi = 0; mi < 2; mi++)
                #pragma unroll
                for (int nj = 0; nj < 8; nj++)
                    mma_bf16(accS[mi][nj], qa[kb][mi], bfr[nj]);
        }

        float mx[2][2];
        #pragma unroll
        for (int mi = 0; mi < 2; mi++)
            #pragma unroll
            for (int hh = 0; hh < 2; hh++) {
                float m = -1e30f;
                #pragma unroll
                for (int nj = 0; nj < 8; nj++)
                    m = fmaxf(m, fmaxf(accS[mi][nj][hh * 2], accS[mi][nj][hh * 2 + 1]));
                m = fmaxf(m, __shfl_xor_sync(0xffffffffu, m, 1));
                m = fmaxf(m, __shfl_xor_sync(0xffffffffu, m, 2));
                mx[mi][hh] = m;
            }
        if (tg == 0) {
            #pragma unroll
            for (int mi = 0; mi < 2; mi++)
                #pragma unroll
                for (int hh = 0; hh < 2; hh++)
                    rmax[wn * 128 + wm * 32 + mi * 16 + hh * 8 + g] = mx[mi][hh];
        }
        __syncthreads();

        float fsc[2][2], mnew[2][2], ls[2][2];
        #pragma unroll
        for (int mi = 0; mi < 2; mi++)
            #pragma unroll
            for (int hh = 0; hh < 2; hh++) {
                int r = wm * 32 + mi * 16 + hh * 8 + g;
                float tm = fmaxf(rmax[r], rmax[128 + r]);
                float mn = fmaxf(m_run[mi][hh], tm);
                mnew[mi][hh] = mn;
                fsc[mi][hh] = __expf(m_run[mi][hh] - mn);
                ls[mi][hh] = 0.f;
            }
        #pragma unroll
        for (int mi = 0; mi < 2; mi++)
            #pragma unroll
            for (int hh = 0; hh < 2; hh++) {
                float mn = mnew[mi][hh];
                float s = 0.f;
                #pragma unroll
                for (int nj = 0; nj < 8; nj++) {
                    float p0 = __expf(accS[mi][nj][hh * 2] - mn);
                    float p1 = __expf(accS[mi][nj][hh * 2 + 1] - mn);
                    accS[mi][nj][hh * 2] = p0;
                    accS[mi][nj][hh * 2 + 1] = p1;
                    s += p0 + p1;
                }
                ls[mi][hh] = s;
                float f = fsc[mi][hh];
                #pragma unroll
                for (int nj2 = 0; nj2 < 4; nj2++) {
                    accO[mi][nj2][hh * 2] *= f;
                    accO[mi][nj2][hh * 2 + 1] *= f;
                }
            }
        #pragma unroll
        for (int mi = 0; mi < 2; mi++)
            #pragma unroll
            for (int hh = 0; hh < 2; hh++) {
                float s = ls[mi][hh];
                s += __shfl_xor_sync(0xffffffffu, s, 1);
                s += __shfl_xor_sync(0xffffffffu, s, 2);
                ls[mi][hh] = s;
            }
        if (tg == 0) {
            #pragma unroll
            for (int mi = 0; mi < 2; mi++)
                #pragma unroll
                for (int hh = 0; hh < 2; hh++)
                    rsum[wn * 128 + wm * 32 + mi * 16 + hh * 8 + g] = ls[mi][hh];
        }
        __syncthreads();
        #pragma unroll
        for (int mi = 0; mi < 2; mi++)
            #pragma unroll
            for (int hh = 0; hh < 2; hh++) {
                int r = wm * 32 + mi * 16 + hh * 8 + g;
                l_run[mi][hh] = l_run[mi][hh] * fsc[mi][hh] + rsum[r] + rsum[128 + r];
                m_run[mi][hh] = mnew[mi][hh];
            }

        #pragma unroll
        for (int kb = 0; kb < 4; kb++) {
            uint32_t pah[2][4], pal[2][4];
            #pragma unroll
            for (int mi = 0; mi < 2; mi++) {
                float x0 = accS[mi][2 * kb][0], x1 = accS[mi][2 * kb][1];
                float x2 = accS[mi][2 * kb][2], x3 = accS[mi][2 * kb][3];
                float y0 = accS[mi][2 * kb + 1][0], y1 = accS[mi][2 * kb + 1][1];
                float y2 = accS[mi][2 * kb + 1][2], y3 = accS[mi][2 * kb + 1][3];
                pah[mi][0] = packh(x0, x1);
                pah[mi][1] = packh(x2, x3);
                pah[mi][2] = packh(y0, y1);
                pah[mi][3] = packh(y2, y3);
                __nv_bfloat162 t0 = *(__nv_bfloat162*)&pah[mi][0];
                __nv_bfloat162 t1 = *(__nv_bfloat162*)&pah[mi][1];
                __nv_bfloat162 t2 = *(__nv_bfloat162*)&pah[mi][2];
                __nv_bfloat162 t3 = *(__nv_bfloat162*)&pah[mi][3];
                pal[mi][0] = packh(x0 - __bfloat162float(t0.x), x1 - __bfloat162float(t0.y));
                pal[mi][1] = packh(x2 - __bfloat162float(t1.x), x3 - __bfloat162float(t1.y));
                pal[mi][2] = packh(y0 - __bfloat162float(t2.x), y1 - __bfloat162float(t2.y));
                pal[mi][3] = packh(y2 - __bfloat162float(t3.x), y3 - __bfloat162float(t3.y));
            }
            uint32_t vbh[4][2], vbl[4][2];
            int kcol = (wn * 64 + kb * 16 + tg * 2) * 2;
            #pragma unroll
            for (int nj2 = 0; nj2 < 4; nj2++) {
                uint32_t bh = sb + OFF_VTH + (nj2 * 8 + g) * SV + kcol;
                uint32_t bl = sb + OFF_VTL + (nj2 * 8 + g) * SV + kcol;
                vbh[nj2][0] = lds32(bh);  vbh[nj2][1] = lds32(bh + 16);
                vbl[nj2][0] = lds32(bl);  vbl[nj2][1] = lds32(bl + 16);
            }
            #pragma unroll
            for (int mi = 0; mi < 2; mi++)
                #pragma unroll
                for (int nj2 = 0; nj2 < 4; nj2++) {
                    mma_bf16(accO[mi][nj2], pah[mi], vbh[nj2]);
                    mma_bf16(accO[mi][nj2], pah[mi], vbl[nj2]);
                    mma_bf16(accO[mi][nj2], pal[mi], vbh[nj2]);
                }
        }
    }

    // ---- cross-warp O reduction + normalize + fp16 store to oS ----
    __syncthreads();
    float* Ob = (float*)smem;
    if (wn == 0) {
        #pragma unroll
        for (int mi = 0; mi < 2; mi++)
            #pragma unroll
            for (int hh = 0; hh < 2; hh++) {
                int r = wm * 32 + mi * 16 + hh * 8 + g;
                #pragma unroll
                for (int nj2 = 0; nj2 < 4; nj2++) {
                    Ob[r * 36 + nj2 * 8 + tg * 2]     = accO[mi][nj2][hh * 2];
                    Ob[r * 36 + nj2 * 8 + tg * 2 + 1] = accO[mi][nj2][hh * 2 + 1];
                }
            }
    }
    __syncthreads();
    if (wn == 1) {
        #pragma unroll
        for (int mi = 0; mi < 2; mi++)
            #pragma unroll
            for (int hh = 0; hh < 2; hh++) {
                int r = wm * 32 + mi * 16 + hh * 8 + g;
                float inv = 1.f / l_run[mi][hh];
                #pragma unroll
                for (int nj2 = 0; nj2 < 4; nj2++) {
                    int d = nj2 * 8 + tg * 2;
                    float v0 = (Ob[r * 36 + d]     + accO[mi][nj2][hh * 2])     * inv;
                    float v1 = (Ob[r * 36 + d + 1] + accO[mi][nj2][hh * 2 + 1]) * inv;
                    long long base = (long long)(b * 1024 + q0 + r) * 256 + h * 32 + d;
                    *(__half2*)&oS[base] = __floats2half2_rn(v0, v1);
                }
            }
    }
}

// ======================= depthwise conv + SiLU, fused fp16 outputs =======================
__global__ void __launch_bounds__(256) conv_silu_kernel(
    const float* __restrict__ xzy,
    const float* __restrict__ wx, const float* __restrict__ wz, const float* __restrict__ wy,
    float* __restrict__ xc, __half* __restrict__ xcS,
    __half* __restrict__ catS, __half* __restrict__ ycS)
{
    int idx = blockIdx.x * 256 + threadIdx.x;
    int d = idx & 255;
    int m = idx >> 8;
    int l = m & 1023;
    const float* base = xzy + (long long)m * 768;
    float a0 = 0.f, a1 = 0.f, a2 = 0.f;
    #pragma unroll
    for (int k = 0; k < 4; k++) {
        int li = l + k - 1;
        if (li < 0 || li >= 1024) continue;
        const float* row = base + (long long)(k - 1) * 768;
        a0 = fmaf(row[d],       wx[d * 4 + k], a0);
        a1 = fmaf(row[256 + d], wz[d * 4 + k], a1);
        a2 = fmaf(row[512 + d], wy[d * 4 + k], a2);
    }
    a0 = a0 / (1.f + __expf(-a0));
    a1 = a1 / (1.f + __expf(-a1));
    a2 = a2 / (1.f + __expf(-a2));
    xc[idx] = a0;
    xcS[(long long)m * 256 + d] = __float2half_rn(a0);
    catS[(long long)m * 768 + 256 + d] = __float2half_rn(a1);
    ycS[(long long)m * 256 + d] = __float2half_rn(a2);
}

// ======================= selective scan (writes fp16 into catS cols [0,256)) ==============
__global__ void __launch_bounds__(256) scan_kernel(
    const float* __restrict__ delta, const float* __restrict__ xc,
    const float* __restrict__ xdbl, const float* __restrict__ A_log,
    const float* __restrict__ D_param, __half* __restrict__ catS)
{
    int t = blockIdx.x * 256 + threadIdx.x;
    int lane = t & 15;
    int p = t >> 4;
    int b = p >> 8;
    int d = p & 255;
    float Acoef = -__expf(A_log[d * 16 + lane]);
    float Dd = D_param[d];
    float h = 0.f;
    const float* dptr = delta + (long long)b * 1024 * 256 + d;
    const float* xptr = xc    + (long long)b * 1024 * 256 + d;
    const float* bptr = xdbl  + (long long)b * 1024 * 80 + 48 + lane;
    const float* cptr = bptr + 16;
    __half* optr = catS + (long long)b * 1024 * 768 + d;
    #pragma unroll 4
    for (int l = 0; l < 1024; l++) {
        float dl = dptr[(long long)l * 256];
        float xv = xptr[(long long)l * 256];
        float Bv = bptr[(long long)l * 80];
        float Cv = cptr[(long long)l * 80];
        float dA = __expf(dl * Acoef);
        h = fmaf(dA, h, dl * xv * Bv);
        float yv = h * Cv;
        yv += __shfl_xor_sync(0xffffffffu, yv, 1);
        yv += __shfl_xor_sync(0xffffffffu, yv, 2);
        yv += __shfl_xor_sync(0xffffffffu, yv, 4);
        yv += __shfl_xor_sync(0xffffffffu, yv, 8);
        if (lane == 0) {
            float v = fmaf(xv, Dd, yv);
            optr[(long long)l * 768] = __float2half_rn(v);
        }
    }
}

// ======================= host launcher =======================
extern "C" void kernel_launch(void* const* d_in, const int* in_sizes, int n_in,
                              void* d_out, int out_size)
{
    const float* hs          = (const float*)d_in[0];
    const float* in_proj_w   = (const float*)d_in[1];
    const float* conv_wx     = (const float*)d_in[2];
    const float* conv_wz     = (const float*)d_in[3];
    const float* conv_wy     = (const float*)d_in[4];
    const float* x_proj_w    = (const float*)d_in[5];
    const float* dt_proj_w   = (const float*)d_in[6];
    const float* dt_proj_b   = (const float*)d_in[7];
    const float* A_log       = (const float*)d_in[8];
    const float* D_param     = (const float*)d_in[9];
    const float* out_proj_w  = (const float*)d_in[10];
    const float* qkv_w       = (const float*)d_in[11];
    const float* attn_proj_w = (const float*)d_in[12];
    const float* attn_proj_b = (const float*)d_in[13];
    float* out = (float*)d_out;

    float *xzy, *xc, *xdbl, *delta, *qkv;
    cudaGetSymbolAddress((void**)&xzy,   g_xzy);
    cudaGetSymbolAddress((void**)&xc,    g_xc);
    cudaGetSymbolAddress((void**)&xdbl,  g_xdbl);
    cudaGetSymbolAddress((void**)&delta, g_delta);
    cudaGetSymbolAddress((void**)&qkv,   g_qkv);

    __half *hsS, *winS, *xcS, *wxpS, *dtS, *wdtS, *ycS, *wqkvS;
    __half *oS, *watS, *catS, *woutS;
    cudaGetSymbolAddress((void**)&hsS,   g_hsS);
    cudaGetSymbolAddress((void**)&winS,  g_winS);
    cudaGetSymbolAddress((void**)&xcS,   g_xcS);
    cudaGetSymbolAddress((void**)&wxpS,  g_wxpS);
    cudaGetSymbolAddress((void**)&dtS,   g_dtS);
    cudaGetSymbolAddress((void**)&wdtS,  g_wdtS);
    cudaGetSymbolAddress((void**)&ycS,   g_ycS);
    cudaGetSymbolAddress((void**)&wqkvS, g_wqkvS);
    cudaGetSymbolAddress((void**)&oS,    g_oS);
    cudaGetSymbolAddress((void**)&watS,  g_watS);
    cudaGetSymbolAddress((void**)&catS,  g_catS);
    cudaGetSymbolAddress((void**)&woutS, g_woutS);

    // 1) input + all-weight fp16 conversions
    half_kernel<<<12288, 256>>>(hs, 768, 4096, 768, hsS);
    weight_half_kernel<<<5760, 256>>>(in_proj_w, x_proj_w, dt_proj_w, qkv_w,
        attn_proj_w, out_proj_w, winS, wxpS, wdtS, wqkvS, watS, woutS);

    // 2) in_proj: xzy = hs @ in_proj_w^T   (K=768)
    gemm_mma<<<dim3(12, 32), 256>>>(hsS, winS, xzy, 4096, 768, 768,
        768, 768, 768, 0, nullptr, 0.f, 1.f, 0, 0,
        nullptr, nullptr, nullptr, 0, 0, 0);

    // 3) depthwise conv + SiLU (fused fp16 outputs)
    conv_silu_kernel<<<4096, 256>>>(xzy, conv_wx, conv_wz, conv_wy, xc, xcS, catS, ycS);

    // 4) DUAL: qkv = yc @ qkv_w^T (bx<12)  ‖  x_dbl = xc @ x_proj_w^T (bx>=12)   (K=256)
    gemm_mma<<<dim3(14, 32), 256>>>(ycS, wqkvS, qkv, 4096, 768, 256,
        256, 256, 768, 0, nullptr, 0.f, 1.f, 0, 0,
        xcS, wxpS, xdbl, 80, 80, 12);

    // 5) fused flash attention -> oS (fp16)
    flash_kernel<<<dim3(8, 32), 256>>>(qkv, oS);

    // 6) dt fp16 + delta = softplus(dt @ dt_proj_w^T + 2*b)   (K=48)
    half_kernel<<<768, 256>>>(xdbl, 80, 4096, 48, dtS);
    gemm_mma<<<dim3(4, 32), 256>>>(dtS, wdtS, delta, 4096, 256, 48,
        48, 48, 256, 0, dt_proj_b, 2.f, 1.f, 2, 0,
        nullptr, nullptr, nullptr, 0, 0, 0);

    // 7) selective scan -> catS cols [0,256) (fp16)
    scan_kernel<<<64, 256>>>(delta, xc, xdbl, A_log, D_param, catS);

    // 8) y_att = o @ attn_proj_w^T + b -> catS cols [512,768) (fp16 epilogue)
    gemm_mma<<<dim3(4, 32), 256>>>(oS, watS, (float*)catS, 4096, 256, 256,
        256, 256, 768, 512, attn_proj_b, 1.f, 1.f, 1, 1,
        nullptr, nullptr, nullptr, 0, 0, 0);

    // 9) out = catS @ out_proj_w^T   (K=768)
    gemm_mma<<<dim3(12, 32), 256>>>(catS, woutS, out, 4096, 768, 768,
        768, 768, 768, 0, nullptr, 0.f, 1.f, 0, 0,
        nullptr, nullptr, nullptr, 0, 0, 0);
}

// round 12
// speedup vs baseline: 1.8597x; 1.1210x over previous
#include <cuda_runtime.h>
#include <cuda_bf16.h>
#include <cuda_fp16.h>
#include <math.h>
#include <stdint.h>

// Problem constants: B=4, L=1024, DM=768, DC=256, N=16, R=48, K=4, H=8, HD=32
// GEMMs + flash attention: single-pass fp16 operands, fp32 accumulate.

// ======================= scratch buffers (static; no allocation) =======================
__device__ float g_xzy[4096 * 768];
__device__ float g_xc[4096 * 256];
__device__ float g_xdbl[4096 * 80];
__device__ float g_delta[4096 * 256];

__device__ __half g_qkvh[4096 * 768];
__device__ __half g_hsS[4096 * 768];
__device__ __half g_winS[768 * 768];
__device__ __half g_xcS[4096 * 256];
__device__ __half g_wxpS[80 * 256];
__device__ __half g_dtS[4096 * 48];
__device__ __half g_wdtS[256 * 48];
__device__ __half g_ycS[4096 * 256];
__device__ __half g_wqkvS[768 * 256];
__device__ __half g_oS[4096 * 256];
__device__ __half g_watS[256 * 256];
__device__ __half g_catS[4096 * 768];
__device__ __half g_woutS[768 * 768];

// ======================= small asm helpers =======================
__device__ __forceinline__ uint32_t smem_to_u32(const void* smem_ptr) {
    uint32_t addr;
    asm("{ .reg .u64 tmp; cvta.to.shared.u64 tmp, %1; cvt.u32.u64 %0, tmp; }"
        : "=r"(addr) : "l"(smem_ptr));
    return addr;
}

__device__ __forceinline__ uint32_t lds32(uint32_t a) {
    uint32_t v;
    asm volatile("ld.shared.b32 %0, [%1];" : "=r"(v) : "r"(a));
    return v;
}

__device__ __forceinline__ void ldsm4(uint32_t* r, uint32_t a) {
    asm volatile("ldmatrix.sync.aligned.m8n8.x4.shared.b16 {%0,%1,%2,%3}, [%4];"
                 : "=r"(r[0]), "=r"(r[1]), "=r"(r[2]), "=r"(r[3]) : "r"(a));
}

__device__ __forceinline__ void cp16(uint32_t dst, const void* src, bool pred) {
    int sz = pred ? 16 : 0;
    asm volatile("cp.async.cg.shared.global [%0], [%1], 16, %2;"
                 :: "r"(dst), "l"(src), "r"(sz) : "memory");
}

__device__ __forceinline__ void mma_f16(float* c, const uint32_t* a, const uint32_t* b) {
    asm volatile(
        "mma.sync.aligned.m16n8k16.row.col.f32.f16.f16.f32 "
        "{%0,%1,%2,%3}, {%4,%5,%6,%7}, {%8,%9}, {%0,%1,%2,%3};"
        : "+f"(c[0]), "+f"(c[1]), "+f"(c[2]), "+f"(c[3])
        : "r"(a[0]), "r"(a[1]), "r"(a[2]), "r"(a[3]), "r"(b[0]), "r"(b[1]));
}

__device__ __forceinline__ uint32_t packf16(float x, float y) {
    __half2 t = __floats2half2_rn(x, y);
    return *(uint32_t*)&t;
}

// ======================= fp32 -> fp16 conversion =======================
__global__ void __launch_bounds__(256) half_kernel(
    const float* __restrict__ src, int ld,
    int M, int K, __half* __restrict__ dst)
{
    int idx = blockIdx.x * 256 + threadIdx.x;
    if (idx >= M * K) return;
    int m = idx / K, k = idx - m * K;
    dst[(long long)m * K + k] = __float2half_rn(src[(long long)m * ld + k]);
}

// ======================= merged weight conversions (ld==K contiguous) ==================
__global__ void __launch_bounds__(256) weight_half_kernel(
    const float* __restrict__ w_in, const float* __restrict__ w_xp,
    const float* __restrict__ w_dt, const float* __restrict__ w_qkv,
    const float* __restrict__ w_at, const float* __restrict__ w_out,
    __half* __restrict__ winS, __half* __restrict__ wxpS,
    __half* __restrict__ wdtS, __half* __restrict__ wqkvS,
    __half* __restrict__ watS, __half* __restrict__ woutS)
{
    int idx = blockIdx.x * 256 + threadIdx.x;
    const float* src; __half* dst;
    int rem = idx;
    if (rem < 589824)                 { src = w_in;  dst = winS;  }
    else if ((rem -= 589824) < 20480) { src = w_xp;  dst = wxpS;  }
    else if ((rem -= 20480) < 12288)  { src = w_dt;  dst = wdtS;  }
    else if ((rem -= 12288) < 196608) { src = w_qkv; dst = wqkvS; }
    else if ((rem -= 196608) < 65536) { src = w_at;  dst = watS;  }
    else                              { rem -= 65536; src = w_out; dst = woutS; }
    dst[rem] = __float2half_rn(src[rem]);
}

// ======================= HMMA fp16 NT GEMM, 128x64x32, 3-stage + ldmatrix ====================
// epi: 0 none, 1 +bias*bscale, 2 softplus(v + bias*bscale)
// ohalf: if 1, C is a __half buffer; write fp16 at coff+c (row stride ldc elements).
// dual: if splitx>0 and blockIdx.x>=splitx, switch to (A2,B2,C2,N2,ldc2), epi=0.
#define ASTR 80
#define STG 15360      // 128*80 (A) + 64*80 (B)
__global__ void __launch_bounds__(256, 3) gemm_mma(
    const __half* __restrict__ A, const __half* __restrict__ B,
    float* __restrict__ C, int M, int Nglob, int Kp,
    int lda, int ldb, int ldc, int coff,
    const float* __restrict__ bias, float bscale, float alpha, int epi,
    int ohalf,
    const __half* __restrict__ A2, const __half* __restrict__ B2,
    float* __restrict__ C2, int N2, int ldc2, int splitx)
{
    __shared__ __align__(16) char smem[3 * STG];
    uint32_t sb = smem_to_u32(smem);
    int tid = threadIdx.x;
    int bx = blockIdx.x;
    int n0;
    if (splitx && bx >= splitx) {
        A = A2; B = B2; C = C2; Nglob = N2; ldc = ldc2;
        epi = 0; ohalf = 0; coff = 0;
        n0 = (bx - splitx) * 64;
    } else {
        n0 = bx * 64;
    }
    int m0 = blockIdx.y * 128;
    int NC = (Kp + 31) >> 5;

    auto load_stage = [&](int c) {
        int k0 = c * 32;
        uint32_t ab = sb + (c % 3) * STG;
        uint32_t bb = ab + 10240;
        #pragma unroll
        for (int i = 0; i < 2; i++) {
            int gg = tid + i * 256;
            int r = gg >> 2, c16 = gg & 3;
            int k = k0 + c16 * 8;
            cp16(ab + r * ASTR + c16 * 16, A + (long long)(m0 + r) * lda + k, k < Kp);
        }
        {
            int r = tid >> 2, c16 = tid & 3;
            int k = k0 + c16 * 8;
            cp16(bb + r * ASTR + c16 * 16, B + (long long)(n0 + r) * ldb + k,
                 (n0 + r) < Nglob && k < Kp);
        }
        asm volatile("cp.async.commit_group;" ::: "memory");
    };

    int wid = tid >> 5, lane = tid & 31;
    int wm = wid & 3, wn = wid >> 2;          // 4x2 warps, warp tile 32x32
    int g = lane >> 2, tg = lane & 3;
    int l7 = lane & 7;

    uint32_t aoff0 = (uint32_t)((wm * 32 + l7 + ((lane >> 3) & 1) * 8) * ASTR + (lane >> 4) * 16);
    uint32_t aoff1 = aoff0 + 16 * ASTR;
    uint32_t boff0 = (uint32_t)((wn * 32 + (lane >> 4) * 8 + l7) * ASTR + ((lane >> 3) & 1) * 16);
    uint32_t boff1 = boff0 + 16 * ASTR;

    float acc[2][4][4] = {};

    load_stage(0);
    if (1 < NC) load_stage(1);

    for (int c = 0; c < NC; c++) {
        if (c + 1 < NC) { asm volatile("cp.async.wait_group 1;" ::: "memory"); }
        else            { asm volatile("cp.async.wait_group 0;" ::: "memory"); }
        __syncthreads();
        if (c + 2 < NC) load_stage(c + 2);

        uint32_t ab = sb + (c % 3) * STG;
        uint32_t bb = ab + 10240;
        #pragma unroll
        for (int ks = 0; ks < 2; ks++) {
            uint32_t a0[4], a1[4], b0[4], b1[4];
            ldsm4(a0, ab + aoff0 + ks * 32);
            ldsm4(a1, ab + aoff1 + ks * 32);
            ldsm4(b0, bb + boff0 + ks * 32);
            ldsm4(b1, bb + boff1 + ks * 32);
            mma_f16(acc[0][0], a0, b0 + 0);
            mma_f16(acc[0][1], a0, b0 + 2);
            mma_f16(acc[0][2], a0, b1 + 0);
            mma_f16(acc[0][3], a0, b1 + 2);
            mma_f16(acc[1][0], a1, b0 + 0);
            mma_f16(acc[1][1], a1, b0 + 2);
            mma_f16(acc[1][2], a1, b1 + 0);
            mma_f16(acc[1][3], a1, b1 + 2);
        }
    }
    __syncthreads();

    // ---- epilogue ----
    #pragma unroll
    for (int mi = 0; mi < 2; mi++) {
        int r0 = m0 + wm * 32 + mi * 16 + g;
        #pragma unroll
        for (int nj = 0; nj < 4; nj++) {
            int cc = n0 + wn * 32 + nj * 8 + tg * 2;
            if (cc >= Nglob) continue;
            #pragma unroll
            for (int hh = 0; hh < 2; hh++) {
                int rr = r0 + hh * 8;
                float v0 = acc[mi][nj][hh * 2 + 0] * alpha;
                float v1 = acc[mi][nj][hh * 2 + 1] * alpha;
                if (epi >= 1) { v0 += bias[cc] * bscale; v1 += bias[cc + 1] * bscale; }
                if (epi == 2) {
                    v0 = (v0 > 15.f) ? v0 : log1pf(__expf(v0));
                    v1 = (v1 > 15.f) ? v1 : log1pf(__expf(v1));
                }
                if (!ohalf) {
                    *(float2*)&C[(long long)rr * ldc + coff + cc] = make_float2(v0, v1);
                } else {
                    __half* Cb = (__half*)C;
                    long long base = (long long)rr * ldc + coff + cc;
                    *(__half2*)&Cb[base] = __floats2half2_rn(v0, v1);
                }
            }
        }
    }
}

// ======================= fused flash attention, single-pass fp16 =======================
// qkvh: fp16 (4096 x 768) [q|k|v]. Q tile 128 rows, K tiles 128 keys, HD=32.
#define FQK 80                    // 32 halfs (64B) + 16 pad
#define OFF_VT 10240              // V^T: 32 x 272
#define FSV 272
#define OFF_FRMAX 18944
#define OFF_FRSUM 19968
__global__ void __launch_bounds__(256) flash_kernel(
    const __half* __restrict__ qkvh, __half* __restrict__ oS)
{
    __shared__ __align__(16) char smem[20992];
    uint32_t sb = smem_to_u32(smem);
    float* rmax = (float*)(smem + OFF_FRMAX);   // [2][128]
    float* rsum = (float*)(smem + OFF_FRSUM);   // [2][128]
    int tid = threadIdx.x;
    int wid = tid >> 5, lane = tid & 31;
    int wm = wid & 3, wn = wid >> 2;
    int g = lane >> 2, tg = lane & 3;
    int z = blockIdx.y;
    int b = z >> 3, h = z & 7;
    int q0 = blockIdx.x * 128;
    const float alpha = 0.17677669529663687f;   // HD^-0.5
    const __half* qkvb = qkvh + (long long)b * 1024 * 768 + h * 32;

    // ---- stage Q (pre-scaled) ----
    #pragma unroll
    for (int j = 0; j < 16; j++) {
        int i = tid + j * 256;
        int row = i >> 5, d = i & 31;
        float f = __half2float(qkvb[(long long)(q0 + row) * 768 + d]) * alpha;
        *(__half*)(smem + row * FQK + d * 2) = __float2half_rn(f);
    }
    __syncthreads();
    // ---- Q A-frags to registers (persistent) ----
    uint32_t qa[2][2][4];
    #pragma unroll
    for (int kb = 0; kb < 2; kb++)
        #pragma unroll
        for (int mi = 0; mi < 2; mi++) {
            uint32_t base = sb + (wm * 32 + mi * 16 + g) * FQK + kb * 32 + tg * 4;
            qa[kb][mi][0] = lds32(base);
            qa[kb][mi][1] = lds32(base + 8 * FQK);
            qa[kb][mi][2] = lds32(base + 16);
            qa[kb][mi][3] = lds32(base + 8 * FQK + 16);
        }

    float accO[2][4][4] = {};
    float m_run[2][2] = {{-1e30f, -1e30f}, {-1e30f, -1e30f}};
    float l_run[2][2] = {{0.f, 0.f}, {0.f, 0.f}};

    for (int t = 0; t < 8; t++) {
        int j0 = t * 128;
        __syncthreads();      // previous tile's consumers done; Q frags live in regs
        // ---- K tile via cp.async (natural [key][d] = B operand layout) ----
        #pragma unroll
        for (int i = 0; i < 2; i++) {
            int gg = tid + i * 256;
            int r = gg >> 2, c16 = gg & 3;
            cp16(sb + r * FQK + c16 * 16,
                 qkvb + (long long)(j0 + r) * 768 + 256 + c16 * 8, true);
        }
        asm volatile("cp.async.commit_group;" ::: "memory");
        // ---- V^T scalar transpose copies ----
        #pragma unroll
        for (int j = 0; j < 16; j++) {
            int i = tid + j * 256;
            int key = i >> 5, d = i & 31;
            *(__half*)(smem + OFF_VT + d * FSV + key * 2) =
                qkvb[(long long)(j0 + key) * 768 + 512 + d];
        }
        asm volatile("cp.async.wait_group 0;" ::: "memory");
        __syncthreads();

        // ---- S = Q @ K^T ----
        float accS[2][8][4] = {};
        #pragma unroll
        for (int kb = 0; kb < 2; kb++) {
            uint32_t bfr[8][2];
            #pragma unroll
            for (int nj = 0; nj < 8; nj++) {
                uint32_t base = sb + (wn * 64 + nj * 8 + g) * FQK + kb * 32 + tg * 4;
                bfr[nj][0] = lds32(base);
                bfr[nj][1] = lds32(base + 16);
            }
            #pragma unroll
            for (int mi = 0; mi < 2; mi++)
                #pragma unroll
                for (int nj = 0; nj < 8; nj++)
                    mma_f16(accS[mi][nj], qa[kb][mi], bfr[nj]);
        }

        // ---- online softmax (fp32 machinery) ----
        float mx[2][2];
        #pragma unroll
        for (int mi = 0; mi < 2; mi++)
            #pragma unroll
            for (int hh = 0; hh < 2; hh++) {
                float m = -1e30f;
                #pragma unroll
                for (int nj = 0; nj < 8; nj++)
                    m = fmaxf(m, fmaxf(accS[mi][nj][hh * 2], accS[mi][nj][hh * 2 + 1]));
                m = fmaxf(m, __shfl_xor_sync(0xffffffffu, m, 1));
                m = fmaxf(m, __shfl_xor_sync(0xffffffffu, m, 2));
                mx[mi][hh] = m;
            }
        if (tg == 0) {
            #pragma unroll
            for (int mi = 0; mi < 2; mi++)
                #pragma unroll
                for (int hh = 0; hh < 2; hh++)
                    rmax[wn * 128 + wm * 32 + mi * 16 + hh * 8 + g] = mx[mi][hh];
        }
        __syncthreads();

        float fsc[2][2], mnew[2][2], ls[2][2];
        #pragma unroll
        for (int mi = 0; mi < 2; mi++)
            #pragma unroll
            for (int hh = 0; hh < 2; hh++) {
                int r = wm * 32 + mi * 16 + hh * 8 + g;
                float tm = fmaxf(rmax[r], rmax[128 + r]);
                float mn = fmaxf(m_run[mi][hh], tm);
                mnew[mi][hh] = mn;
                fsc[mi][hh] = __expf(m_run[mi][hh] - mn);
                ls[mi][hh] = 0.f;
            }
        #pragma unroll
        for (int mi = 0; mi < 2; mi++)
            #pragma unroll
            for (int hh = 0; hh < 2; hh++) {
                float mn = mnew[mi][hh];
                float s = 0.f;
                #pragma unroll
                for (int nj = 0; nj < 8; nj++) {
                    float p0 = __expf(accS[mi][nj][hh * 2] - mn);
                    float p1 = __expf(accS[mi][nj][hh * 2 + 1] - mn);
                    accS[mi][nj][hh * 2] = p0;
                    accS[mi][nj][hh * 2 + 1] = p1;
                    s += p0 + p1;
                }
                ls[mi][hh] = s;
                float f = fsc[mi][hh];
                #pragma unroll
                for (int nj2 = 0; nj2 < 4; nj2++) {
                    accO[mi][nj2][hh * 2] *= f;
                    accO[mi][nj2][hh * 2 + 1] *= f;
                }
            }
        #pragma unroll
        for (int mi = 0; mi < 2; mi++)
            #pragma unroll
            for (int hh = 0; hh < 2; hh++) {
                float s = ls[mi][hh];
                s += __shfl_xor_sync(0xffffffffu, s, 1);
                s += __shfl_xor_sync(0xffffffffu, s, 2);
                ls[mi][hh] = s;
            }
        if (tg == 0) {
            #pragma unroll
            for (int mi = 0; mi < 2; mi++)
                #pragma unroll
                for (int hh = 0; hh < 2; hh++)
                    rsum[wn * 128 + wm * 32 + mi * 16 + hh * 8 + g] = ls[mi][hh];
        }
        __syncthreads();
        #pragma unroll
        for (int mi = 0; mi < 2; mi++)
            #pragma unroll
            for (int hh = 0; hh < 2; hh++) {
                int r = wm * 32 + mi * 16 + hh * 8 + g;
                l_run[mi][hh] = l_run[mi][hh] * fsc[mi][hh] + rsum[r] + rsum[128 + r];
                m_run[mi][hh] = mnew[mi][hh];
            }

        // ---- O += P @ V  (single fp16 pass) ----
        #pragma unroll
        for (int kb = 0; kb < 4; kb++) {
            uint32_t pa[2][4];
            #pragma unroll
            for (int mi = 0; mi < 2; mi++) {
                pa[mi][0] = packf16(accS[mi][2 * kb][0], accS[mi][2 * kb][1]);
                pa[mi][1] = packf16(accS[mi][2 * kb][2], accS[mi][2 * kb][3]);
                pa[mi][2] = packf16(accS[mi][2 * kb + 1][0], accS[mi][2 * kb + 1][1]);
                pa[mi][3] = packf16(accS[mi][2 * kb + 1][2], accS[mi][2 * kb + 1][3]);
            }
            uint32_t vb[4][2];
            int kcol = (wn * 64 + kb * 16 + tg * 2) * 2;
            #pragma unroll
            for (int nj2 = 0; nj2 < 4; nj2++) {
                uint32_t bh = sb + OFF_VT + (nj2 * 8 + g) * FSV + kcol;
                vb[nj2][0] = lds32(bh);
                vb[nj2][1] = lds32(bh + 16);
            }
            #pragma unroll
            for (int mi = 0; mi < 2; mi++)
                #pragma unroll
                for (int nj2 = 0; nj2 < 4; nj2++)
                    mma_f16(accO[mi][nj2], pa[mi], vb[nj2]);
        }
    }

    // ---- cross-warp O reduction + normalize + fp16 store ----
    __syncthreads();
    float* Ob = (float*)smem;   // 128 x 36 floats, overlays Q/K + part of VT
    if (wn == 0) {
        #pragma unroll
        for (int mi = 0; mi < 2; mi++)
            #pragma unroll
            for (int hh = 0; hh < 2; hh++) {
                int r = wm * 32 + mi * 16 + hh * 8 + g;
                #pragma unroll
                for (int nj2 = 0; nj2 < 4; nj2++) {
                    Ob[r * 36 + nj2 * 8 + tg * 2]     = accO[mi][nj2][hh * 2];
                    Ob[r * 36 + nj2 * 8 + tg * 2 + 1] = accO[mi][nj2][hh * 2 + 1];
                }
            }
    }
    __syncthreads();
    if (wn == 1) {
        #pragma unroll
        for (int mi = 0; mi < 2; mi++)
            #pragma unroll
            for (int hh = 0; hh < 2; hh++) {
                int r = wm * 32 + mi * 16 + hh * 8 + g;
                float inv = 1.f / l_run[mi][hh];
                #pragma unroll
                for (int nj2 = 0; nj2 < 4; nj2++) {
                    int d = nj2 * 8 + tg * 2;
                    float v0 = (Ob[r * 36 + d]     + accO[mi][nj2][hh * 2])     * inv;
                    float v1 = (Ob[r * 36 + d + 1] + accO[mi][nj2][hh * 2 + 1]) * inv;
                    long long base = (long long)(b * 1024 + q0 + r) * 256 + h * 32 + d;
                    *(__half2*)&oS[base] = __floats2half2_rn(v0, v1);
                }
            }
    }
}

// ======================= depthwise conv + SiLU, fused fp16 outputs =======================
__global__ void __launch_bounds__(256) conv_silu_kernel(
    const float* __restrict__ xzy,
    const float* __restrict__ wx, const float* __restrict__ wz, const float* __restrict__ wy,
    float* __restrict__ xc, __half* __restrict__ xcS,
    __half* __restrict__ catS, __half* __restrict__ ycS)
{
    int idx = blockIdx.x * 256 + threadIdx.x;
    int d = idx & 255;
    int m = idx >> 8;
    int l = m & 1023;
    const float* base = xzy + (long long)m * 768;
    float a0 = 0.f, a1 = 0.f, a2 = 0.f;
    #pragma unroll
    for (int k = 0; k < 4; k++) {
        int li = l + k - 1;
        if (li < 0 || li >= 1024) continue;
        const float* row = base + (long long)(k - 1) * 768;
        a0 = fmaf(row[d],       wx[d * 4 + k], a0);
        a1 = fmaf(row[256 + d], wz[d * 4 + k], a1);
        a2 = fmaf(row[512 + d], wy[d * 4 + k], a2);
    }
    a0 = a0 / (1.f + __expf(-a0));
    a1 = a1 / (1.f + __expf(-a1));
    a2 = a2 / (1.f + __expf(-a2));
    xc[idx] = a0;
    xcS[(long long)m * 256 + d] = __float2half_rn(a0);
    catS[(long long)m * 768 + 256 + d] = __float2half_rn(a1);
    ycS[(long long)m * 256 + d] = __float2half_rn(a2);
}

// ======================= selective scan (writes fp16 into catS cols [0,256)) ==============
__global__ void __launch_bounds__(256) scan_kernel(
    const float* __restrict__ delta, const float* __restrict__ xc,
    const float* __restrict__ xdbl, const float* __restrict__ A_log,
    const float* __restrict__ D_param, __half* __restrict__ catS)
{
    int t = blockIdx.x * 256 + threadIdx.x;
    int lane = t & 15;
    int p = t >> 4;
    int b = p >> 8;
    int d = p & 255;
    float Acoef = -__expf(A_log[d * 16 + lane]);
    float Dd = D_param[d];
    float h = 0.f;
    const float* dptr = delta + (long long)b * 1024 * 256 + d;
    const float* xptr = xc    + (long long)b * 1024 * 256 + d;
    const float* bptr = xdbl  + (long long)b * 1024 * 80 + 48 + lane;
    const float* cptr = bptr + 16;
    __half* optr = catS + (long long)b * 1024 * 768 + d;
    #pragma unroll 4
    for (int l = 0; l < 1024; l++) {
        float dl = dptr[(long long)l * 256];
        float xv = xptr[(long long)l * 256];
        float Bv = bptr[(long long)l * 80];
        float Cv = cptr[(long long)l * 80];
        float dA = __expf(dl * Acoef);
        h = fmaf(dA, h, dl * xv * Bv);
        float yv = h * Cv;
        yv += __shfl_xor_sync(0xffffffffu, yv, 1);
        yv += __shfl_xor_sync(0xffffffffu, yv, 2);
        yv += __shfl_xor_sync(0xffffffffu, yv, 4);
        yv += __shfl_xor_sync(0xffffffffu, yv, 8);
        if (lane == 0) {
            float v = fmaf(xv, Dd, yv);
            optr[(long long)l * 768] = __float2half_rn(v);
        }
    }
}

// ======================= host launcher =======================
extern "C" void kernel_launch(void* const* d_in, const int* in_sizes, int n_in,
                              void* d_out, int out_size)
{
    const float* hs          = (const float*)d_in[0];
    const float* in_proj_w   = (const float*)d_in[1];
    const float* conv_wx     = (const float*)d_in[2];
    const float* conv_wz     = (const float*)d_in[3];
    const float* conv_wy     = (const float*)d_in[4];
    const float* x_proj_w    = (const float*)d_in[5];
    const float* dt_proj_w   = (const float*)d_in[6];
    const float* dt_proj_b   = (const float*)d_in[7];
    const float* A_log       = (const float*)d_in[8];
    const float* D_param     = (const float*)d_in[9];
    const float* out_proj_w  = (const float*)d_in[10];
    const float* qkv_w       = (const float*)d_in[11];
    const float* attn_proj_w = (const float*)d_in[12];
    const float* attn_proj_b = (const float*)d_in[13];
    float* out = (float*)d_out;

    float *xzy, *xc, *xdbl, *delta;
    cudaGetSymbolAddress((void**)&xzy,   g_xzy);
    cudaGetSymbolAddress((void**)&xc,    g_xc);
    cudaGetSymbolAddress((void**)&xdbl,  g_xdbl);
    cudaGetSymbolAddress((void**)&delta, g_delta);

    __half *qkvh, *hsS, *winS, *xcS, *wxpS, *dtS, *wdtS, *ycS, *wqkvS;
    __half *oS, *watS, *catS, *woutS;
    cudaGetSymbolAddress((void**)&qkvh,  g_qkvh);
    cudaGetSymbolAddress((void**)&hsS,   g_hsS);
    cudaGetSymbolAddress((void**)&winS,  g_winS);
    cudaGetSymbolAddress((void**)&xcS,   g_xcS);
    cudaGetSymbolAddress((void**)&wxpS,  g_wxpS);
    cudaGetSymbolAddress((void**)&dtS,   g_dtS);
    cudaGetSymbolAddress((void**)&wdtS,  g_wdtS);
    cudaGetSymbolAddress((void**)&ycS,   g_ycS);
    cudaGetSymbolAddress((void**)&wqkvS, g_wqkvS);
    cudaGetSymbolAddress((void**)&oS,    g_oS);
    cudaGetSymbolAddress((void**)&watS,  g_watS);
    cudaGetSymbolAddress((void**)&catS,  g_catS);
    cudaGetSymbolAddress((void**)&woutS, g_woutS);

    // 1) input + all-weight fp16 conversions
    half_kernel<<<12288, 256>>>(hs, 768, 4096, 768, hsS);
    weight_half_kernel<<<5760, 256>>>(in_proj_w, x_proj_w, dt_proj_w, qkv_w,
        attn_proj_w, out_proj_w, winS, wxpS, wdtS, wqkvS, watS, woutS);

    // 2) in_proj: xzy = hs @ in_proj_w^T   (K=768)
    gemm_mma<<<dim3(12, 32), 256>>>(hsS, winS, xzy, 4096, 768, 768,
        768, 768, 768, 0, nullptr, 0.f, 1.f, 0, 0,
        nullptr, nullptr, nullptr, 0, 0, 0);

    // 3) depthwise conv + SiLU (fused fp16 outputs)
    conv_silu_kernel<<<4096, 256>>>(xzy, conv_wx, conv_wz, conv_wy, xc, xcS, catS, ycS);

    // 4) DUAL: qkv(fp16) = yc @ qkv_w^T (bx<12)  ‖  x_dbl = xc @ x_proj_w^T (bx>=12)   (K=256)
    gemm_mma<<<dim3(14, 32), 256>>>(ycS, wqkvS, (float*)qkvh, 4096, 768, 256,
        256, 256, 768, 0, nullptr, 0.f, 1.f, 0, 1,
        xcS, wxpS, xdbl, 80, 80, 12);

    // 5) fused flash attention (fp16) -> oS
    flash_kernel<<<dim3(8, 32), 256>>>(qkvh, oS);

    // 6) dt fp16 + delta = softplus(dt @ dt_proj_w^T + 2*b)   (K=48)
    half_kernel<<<768, 256>>>(xdbl, 80, 4096, 48, dtS);
    gemm_mma<<<dim3(4, 32), 256>>>(dtS, wdtS, delta, 4096, 256, 48,
        48, 48, 256, 0, dt_proj_b, 2.f, 1.f, 2, 0,
        nullptr, nullptr, nullptr, 0, 0, 0);

    // 7) selective scan -> catS cols [0,256) (fp16)
    scan_kernel<<<64, 256>>>(delta, xc, xdbl, A_log, D_param, catS);

    // 8) y_att = o @ attn_proj_w^T + b -> catS cols [512,768) (fp16 epilogue)
    gemm_mma<<<dim3(4, 32), 256>>>(oS, watS, (float*)catS, 4096, 256, 256,
        256, 256, 768, 512, attn_proj_b, 1.f, 1.f, 1, 1,
        nullptr, nullptr, nullptr, 0, 0, 0);

    // 9) out = catS @ out_proj_w^T   (K=768)
    gemm_mma<<<dim3(12, 32), 256>>>(catS, woutS, out, 4096, 768, 768,
        768, 768, 768, 0, nullptr, 0.f, 1.f, 0, 0,
        nullptr, nullptr, nullptr, 0, 0, 0);
}